// round 1
// baseline (speedup 1.0000x reference)
#include <cuda_runtime.h>
#include <mma.h>
#include <math.h>

using namespace nvcuda;

// Problem constants
#define D_MODEL   1024
#define NUM_HEADS 16
#define HEAD_DIM  64
#define SEQ       2048
#define BATCH     2
#define M_TOTAL   (BATCH * SEQ)   // 4096

// Scratch buffers (no allocation allowed -> __device__ globals)
__device__ float g_q[BATCH * NUM_HEADS * SEQ * HEAD_DIM];    // [B,H,S,Dh]
__device__ float g_k[BATCH * NUM_HEADS * SEQ * HEAD_DIM];
__device__ float g_v[BATCH * NUM_HEADS * SEQ * HEAD_DIM];
__device__ float g_ctx[M_TOTAL * D_MODEL];                   // [B,S,D]

// ---------------------------------------------------------------------------
// tf32 helpers
// ---------------------------------------------------------------------------
template <class Frag>
__device__ __forceinline__ void frag_to_tf32(Frag& f) {
#pragma unroll
    for (int i = 0; i < f.num_elements; i++)
        f.x[i] = wmma::__float_to_tf32(f.x[i]);
}

// ---------------------------------------------------------------------------
// GEMM:  Y = X @ W^T   (X: [M,K] row-major, W: [N,K] row-major)
// MODE 0: QKV projection. blockIdx.z selects (Wq,Wk,Wv) -> (g_q,g_k,g_v),
//         output written in [B,H,S,Dh] layout (BN==HEAD_DIM => one head/CTA col).
// MODE 1: out projection. W = W0, output row-major to Yout (bias added later).
// ---------------------------------------------------------------------------
#define BM  128
#define BN  64
#define BK  16
#define BKP 20   // padded smem row stride (multiple of 4 for wmma ld)

template <int MODE>
__global__ void __launch_bounds__(256)
gemm_tf32_kernel(const float* __restrict__ X,
                 const float* __restrict__ W0,
                 const float* __restrict__ W1,
                 const float* __restrict__ W2,
                 float* __restrict__ Yout)
{
    const float* W;
    float* Y;
    const float* Xp;
    if (MODE == 0) {
        int which = blockIdx.z;
        W  = (which == 0) ? W0 : (which == 1) ? W1 : W2;
        Y  = (which == 0) ? g_q : (which == 1) ? g_k : g_v;
        Xp = X;
    } else {
        W  = W0;
        Y  = Yout;
        Xp = g_ctx;
    }

    __shared__ float As[BM][BKP];
    __shared__ float Bs[BN][BKP];

    const int m0 = blockIdx.y * BM;
    const int n0 = blockIdx.x * BN;
    const int tid  = threadIdx.x;
    const int warp = tid >> 5;
    const int wm = warp & 3;   // 4 warps along M (32 rows each)
    const int wn = warp >> 2;  // 2 warps along N (32 cols each)

    wmma::fragment<wmma::accumulator, 16, 16, 8, float> c[2][2];
#pragma unroll
    for (int i = 0; i < 2; i++)
#pragma unroll
        for (int j = 0; j < 2; j++)
            wmma::fill_fragment(c[i][j], 0.0f);

    // global->smem load assignments
    const int ar  = tid >> 1;        // 0..127
    const int akc = (tid & 1) * 8;   // 0 or 8
    const int br  = tid >> 2;        // 0..63
    const int bkc = (tid & 3) * 4;   // 0,4,8,12

    for (int k0 = 0; k0 < D_MODEL; k0 += BK) {
        // A tile: 128 x 16
        const float4* ap = reinterpret_cast<const float4*>(Xp + (size_t)(m0 + ar) * D_MODEL + k0 + akc);
        float4 av0 = ap[0];
        float4 av1 = ap[1];
        *reinterpret_cast<float4*>(&As[ar][akc])     = av0;
        *reinterpret_cast<float4*>(&As[ar][akc + 4]) = av1;
        // B tile: 64 x 16 (from W rows n0..n0+63)
        *reinterpret_cast<float4*>(&Bs[br][bkc]) =
            *reinterpret_cast<const float4*>(W + (size_t)(n0 + br) * D_MODEL + k0 + bkc);
        __syncthreads();

#pragma unroll
        for (int kk = 0; kk < BK; kk += 8) {
            wmma::fragment<wmma::matrix_a, 16, 16, 8, wmma::precision::tf32, wmma::row_major> a[2];
            wmma::fragment<wmma::matrix_b, 16, 16, 8, wmma::precision::tf32, wmma::col_major> b[2];
#pragma unroll
            for (int i = 0; i < 2; i++) {
                wmma::load_matrix_sync(a[i], &As[wm * 32 + i * 16][kk], BKP);
                frag_to_tf32(a[i]);
            }
#pragma unroll
            for (int j = 0; j < 2; j++) {
                wmma::load_matrix_sync(b[j], &Bs[wn * 32 + j * 16][kk], BKP);
                frag_to_tf32(b[j]);
            }
#pragma unroll
            for (int i = 0; i < 2; i++)
#pragma unroll
                for (int j = 0; j < 2; j++)
                    wmma::mma_sync(c[i][j], a[i], b[j], c[i][j]);
        }
        __syncthreads();
    }

    if (MODE == 0) {
        // n0 spans exactly one head (BN == HEAD_DIM). Row-major store with ld=64
        // into [B,H,S,Dh].
        const int b = m0 / SEQ;          // BM divides SEQ -> no crossing
        const int h = blockIdx.x;        // BN == 64 == HEAD_DIM
        const int sbase = (m0 % SEQ);
#pragma unroll
        for (int i = 0; i < 2; i++)
#pragma unroll
            for (int j = 0; j < 2; j++) {
                int s = sbase + wm * 32 + i * 16;
                int d = wn * 32 + j * 16;
                float* p = Y + ((size_t)(b * NUM_HEADS + h) * SEQ + s) * HEAD_DIM + d;
                wmma::store_matrix_sync(p, c[i][j], HEAD_DIM, wmma::mem_row_major);
            }
    } else {
#pragma unroll
        for (int i = 0; i < 2; i++)
#pragma unroll
            for (int j = 0; j < 2; j++) {
                float* p = Y + (size_t)(m0 + wm * 32 + i * 16) * D_MODEL + n0 + wn * 32 + j * 16;
                wmma::store_matrix_sync(p, c[i][j], D_MODEL, wmma::mem_row_major);
            }
    }
}

// ---------------------------------------------------------------------------
// Fused causal flash attention (fp32 state, tf32 wmma for QK^T and PV)
// One CTA: 64 query rows of one (b,h). grid = (S/64, B*H)
// ---------------------------------------------------------------------------
#define BQ 64
#define SP 68   // padded row stride for score / output tiles

__global__ void __launch_bounds__(256)
attn_kernel()
{
    __shared__ float Ss[BQ][SP];     // scores / probabilities / PV staging
    __shared__ float Os[BQ][SP];     // output accumulator
    __shared__ float m_s[BQ], l_s[BQ], corr_s[BQ];

    // Long CTAs (large qb) first for better wave packing
    const int qb = gridDim.x - 1 - blockIdx.x;
    const int bh = blockIdx.y;
    const float* Q = g_q + (size_t)bh * SEQ * HEAD_DIM;
    const float* K = g_k + (size_t)bh * SEQ * HEAD_DIM;
    const float* V = g_v + (size_t)bh * SEQ * HEAD_DIM;
    const int q0 = qb * BQ;

    const int tid  = threadIdx.x;
    const int warp = tid >> 5;
    const int wm = warp & 3;   // 16 rows / warp
    const int wn = warp >> 2;  // 32 cols / warp
    const int r  = tid >> 2;   // softmax row (0..63)
    const int cq = tid & 3;    // quarter of the row (16 cols)

    if (tid < BQ) { m_s[tid] = -INFINITY; l_s[tid] = 0.0f; }
    for (int i = tid; i < BQ * SP; i += 256) (&Os[0][0])[i] = 0.0f;
    __syncthreads();

    for (int kb = 0; kb <= qb; kb++) {
        // ---- S = Q @ K^T  (operands straight from global; L1/L2 resident) ----
        {
            wmma::fragment<wmma::accumulator, 16, 16, 8, float> cs[2];
#pragma unroll
            for (int j = 0; j < 2; j++) wmma::fill_fragment(cs[j], 0.0f);
#pragma unroll
            for (int kk = 0; kk < HEAD_DIM; kk += 8) {
                wmma::fragment<wmma::matrix_a, 16, 16, 8, wmma::precision::tf32, wmma::row_major> a;
                wmma::load_matrix_sync(a, Q + (size_t)(q0 + wm * 16) * HEAD_DIM + kk, HEAD_DIM);
                frag_to_tf32(a);
#pragma unroll
                for (int j = 0; j < 2; j++) {
                    wmma::fragment<wmma::matrix_b, 16, 16, 8, wmma::precision::tf32, wmma::col_major> b;
                    wmma::load_matrix_sync(b, K + (size_t)(kb * 64 + wn * 32 + j * 16) * HEAD_DIM + kk, HEAD_DIM);
                    frag_to_tf32(b);
                    wmma::mma_sync(cs[j], a, b, cs[j]);
                }
            }
#pragma unroll
            for (int j = 0; j < 2; j++)
                wmma::store_matrix_sync(&Ss[wm * 16][wn * 32 + j * 16], cs[j], SP, wmma::mem_row_major);
        }
        __syncthreads();

        // ---- online softmax over this 64-wide key block ----
        {
            const int qi = q0 + r;
            const bool diag = (kb == qb);
            float xv[16];
            float mx = -INFINITY;
#pragma unroll
            for (int t = 0; t < 16; t++) {
                int c = cq * 16 + t;
                float x = Ss[r][c] * 0.125f;   // 1/sqrt(64)
                if (diag && (kb * 64 + c > qi)) x = -INFINITY;
                xv[t] = x;
                mx = fmaxf(mx, x);
            }
            mx = fmaxf(mx, __shfl_xor_sync(0xFFFFFFFFu, mx, 1));
            mx = fmaxf(mx, __shfl_xor_sync(0xFFFFFFFFu, mx, 2));
            const float mold = m_s[r];
            const float mnew = fmaxf(mold, mx);
            float sum = 0.0f;
#pragma unroll
            for (int t = 0; t < 16; t++) {
                float p = __expf(xv[t] - mnew);
                Ss[r][cq * 16 + t] = p;
                sum += p;
            }
            sum += __shfl_xor_sync(0xFFFFFFFFu, sum, 1);
            sum += __shfl_xor_sync(0xFFFFFFFFu, sum, 2);
            if (cq == 0) {
                float corr = __expf(mold - mnew);
                corr_s[r] = corr;
                m_s[r]    = mnew;
                l_s[r]    = l_s[r] * corr + sum;
            }
        }
        __syncthreads();

        // ---- PV: acc_tile = P @ V ----
        {
            wmma::fragment<wmma::accumulator, 16, 16, 8, float> co[2];
#pragma unroll
            for (int j = 0; j < 2; j++) wmma::fill_fragment(co[j], 0.0f);
#pragma unroll
            for (int kk = 0; kk < 64; kk += 8) {
                wmma::fragment<wmma::matrix_a, 16, 16, 8, wmma::precision::tf32, wmma::row_major> a;
                wmma::load_matrix_sync(a, &Ss[wm * 16][kk], SP);
                frag_to_tf32(a);
#pragma unroll
                for (int j = 0; j < 2; j++) {
                    wmma::fragment<wmma::matrix_b, 16, 16, 8, wmma::precision::tf32, wmma::row_major> b;
                    wmma::load_matrix_sync(b, V + (size_t)(kb * 64 + kk) * HEAD_DIM + wn * 32 + j * 16, HEAD_DIM);
                    frag_to_tf32(b);
                    wmma::mma_sync(co[j], a, b, co[j]);
                }
            }
            __syncthreads();  // all warps done reading P before overwrite
#pragma unroll
            for (int j = 0; j < 2; j++)
                wmma::store_matrix_sync(&Ss[wm * 16][wn * 32 + j * 16], co[j], SP, wmma::mem_row_major);
        }
        __syncthreads();

        // ---- rescale + accumulate into Os ----
        {
            const float corr = corr_s[r];
#pragma unroll
            for (int t = 0; t < 16; t++) {
                int c = cq * 16 + t;
                Os[r][c] = Os[r][c] * corr + Ss[r][c];
            }
        }
        __syncthreads();
    }

    // ---- finalize: ctx[b, s, h*64 + d] = Os / l ----
    {
        const float inv_l = 1.0f / l_s[r];
        const int b = bh / NUM_HEADS;
        const int h = bh % NUM_HEADS;
        float* outp = g_ctx + ((size_t)(b * SEQ + q0 + r)) * D_MODEL + h * HEAD_DIM;
#pragma unroll
        for (int t = 0; t < 16; t++) {
            int c = cq * 16 + t;
            outp[c] = Os[r][c] * inv_l;
        }
    }
}

// ---------------------------------------------------------------------------
// bias add: out[m,n] += b[n]
// ---------------------------------------------------------------------------
__global__ void __launch_bounds__(256)
bias_kernel(float* __restrict__ out, const float* __restrict__ bias)
{
    int i = blockIdx.x * 256 + threadIdx.x;
    out[i] += bias[i & (D_MODEL - 1)];
}

// ---------------------------------------------------------------------------
// launch
// ---------------------------------------------------------------------------
extern "C" void kernel_launch(void* const* d_in, const int* in_sizes, int n_in,
                              void* d_out, int out_size)
{
    const float* x  = (const float*)d_in[0];
    const float* wq = (const float*)d_in[1];
    const float* wk = (const float*)d_in[2];
    const float* wv = (const float*)d_in[3];
    const float* wo = (const float*)d_in[4];
    const float* bo = (const float*)d_in[5];
    float* out = (float*)d_out;

    // QKV projections: grid (N/BN, M/BM, 3)
    dim3 gqkv(D_MODEL / BN, M_TOTAL / BM, 3);
    gemm_tf32_kernel<0><<<gqkv, 256>>>(x, wq, wk, wv, nullptr);

    // fused causal attention
    dim3 gattn(SEQ / BQ, BATCH * NUM_HEADS);
    attn_kernel<<<gattn, 256>>>();

    // out projection
    dim3 gout(D_MODEL / BN, M_TOTAL / BM, 1);
    gemm_tf32_kernel<1><<<gout, 256>>>(nullptr, wo, nullptr, nullptr, out);

    // bias
    bias_kernel<<<(M_TOTAL * D_MODEL) / 256, 256>>>(out, bo);
}

// round 4
// speedup vs baseline: 1.4424x; 1.4424x over previous
#include <cuda_runtime.h>
#include <cstdint>
#include <mma.h>
#include <math.h>

using namespace nvcuda;

// Problem constants
#define D_MODEL   1024
#define NUM_HEADS 16
#define HEAD_DIM  64
#define SEQ       2048
#define BATCH     2
#define M_TOTAL   (BATCH * SEQ)   // 4096

// Scratch buffers (no allocation allowed -> __device__ globals)
__device__ float g_q[BATCH * NUM_HEADS * SEQ * HEAD_DIM];    // [B,H,S,Dh]
__device__ float g_k[BATCH * NUM_HEADS * SEQ * HEAD_DIM];
__device__ float g_v[BATCH * NUM_HEADS * SEQ * HEAD_DIM];
__device__ float g_ctx[M_TOTAL * D_MODEL];                   // [B,S,D]

// ---------------------------------------------------------------------------
// helpers
// ---------------------------------------------------------------------------
template <class Frag>
__device__ __forceinline__ void frag_to_tf32(Frag& f) {
#pragma unroll
    for (int i = 0; i < f.num_elements; i++)
        f.x[i] = wmma::__float_to_tf32(f.x[i]);
}

__device__ __forceinline__ void cp_async16(void* smem_ptr, const void* gmem_ptr) {
    unsigned int s = (unsigned int)__cvta_generic_to_shared(smem_ptr);
    asm volatile("cp.async.cg.shared.global [%0], [%1], 16;\n" :: "r"(s), "l"(gmem_ptr));
}
__device__ __forceinline__ void cp_commit() {
    asm volatile("cp.async.commit_group;\n");
}
__device__ __forceinline__ void cp_wait0() {
    asm volatile("cp.async.wait_group 0;\n");
}
__device__ __forceinline__ void cp_wait1() {
    asm volatile("cp.async.wait_group 1;\n");
}

// ---------------------------------------------------------------------------
// GEMM:  Y = X @ W^T   (X: [M,K] row-major, W: [N,K] row-major)
// 128x128x32 tiles, double-buffered cp.async, tf32 wmma.
// MODE 0: QKV projection -> g_q/g_k/g_v in [B,H,S,Dh] layout.
// MODE 1: out projection -> Yout row-major.
// ---------------------------------------------------------------------------
#define BM  128
#define BN  128
#define BK  32
#define BKP 36   // padded smem row stride (floats); 36*4=144B, 16B-aligned rows
#define GEMM_SMEM_BYTES (2 * (BM + BN) * BKP * 4)   // 73728

template <int MODE>
__global__ void __launch_bounds__(256)
gemm_tf32_db(const float* __restrict__ X,
             const float* __restrict__ W0,
             const float* __restrict__ W1,
             const float* __restrict__ W2,
             float* __restrict__ Yout)
{
    extern __shared__ float sm[];
    float* As = sm;                      // [2][BM][BKP]
    float* Bs = sm + 2 * BM * BKP;       // [2][BN][BKP]

    const float* W;
    float* Y;
    const float* Xp;
    if (MODE == 0) {
        int which = blockIdx.z;
        W  = (which == 0) ? W0 : (which == 1) ? W1 : W2;
        Y  = (which == 0) ? g_q : (which == 1) ? g_k : g_v;
        Xp = X;
    } else {
        W  = W0;
        Y  = Yout;
        Xp = g_ctx;
    }

    const int m0 = blockIdx.y * BM;
    const int n0 = blockIdx.x * BN;
    const int tid  = threadIdx.x;
    const int warp = tid >> 5;
    const int wm = warp >> 1;   // 0..3 : 32 rows each
    const int wn = warp & 1;    // 0..1 : 64 cols each

    wmma::fragment<wmma::accumulator, 16, 16, 8, float> c[2][4];
#pragma unroll
    for (int i = 0; i < 2; i++)
#pragma unroll
        for (int j = 0; j < 4; j++)
            wmma::fill_fragment(c[i][j], 0.0f);

    const int NIT = D_MODEL / BK;   // 32

    auto load_tiles = [&](int it, int buf) {
        const int k0 = it * BK;
        float* Ab = As + buf * BM * BKP;
        float* Bb = Bs + buf * BN * BKP;
#pragma unroll
        for (int j = 0; j < 4; j++) {
            int idx = tid + j * 256;
            int row = idx >> 3;
            int col = (idx & 7) * 4;
            cp_async16(Ab + row * BKP + col,
                       Xp + (size_t)(m0 + row) * D_MODEL + k0 + col);
            cp_async16(Bb + row * BKP + col,
                       W + (size_t)(n0 + row) * D_MODEL + k0 + col);
        }
        cp_commit();
    };

    load_tiles(0, 0);

    for (int it = 0; it < NIT; it++) {
        const int buf = it & 1;
        if (it + 1 < NIT) {
            load_tiles(it + 1, buf ^ 1);
            cp_wait1();
        } else {
            cp_wait0();
        }
        __syncthreads();

        const float* Ab = As + buf * BM * BKP;
        const float* Bb = Bs + buf * BN * BKP;
#pragma unroll
        for (int kk = 0; kk < BK; kk += 8) {
            wmma::fragment<wmma::matrix_a, 16, 16, 8, wmma::precision::tf32, wmma::row_major> a[2];
            wmma::fragment<wmma::matrix_b, 16, 16, 8, wmma::precision::tf32, wmma::col_major> b[4];
#pragma unroll
            for (int i = 0; i < 2; i++) {
                wmma::load_matrix_sync(a[i], Ab + (wm * 32 + i * 16) * BKP + kk, BKP);
                frag_to_tf32(a[i]);
            }
#pragma unroll
            for (int j = 0; j < 4; j++) {
                wmma::load_matrix_sync(b[j], Bb + (wn * 64 + j * 16) * BKP + kk, BKP);
                frag_to_tf32(b[j]);
            }
#pragma unroll
            for (int i = 0; i < 2; i++)
#pragma unroll
                for (int j = 0; j < 4; j++)
                    wmma::mma_sync(c[i][j], a[i], b[j], c[i][j]);
        }
        __syncthreads();
    }

    if (MODE == 0) {
        // BN=128 spans exactly 2 heads; each 16-col fragment stays inside one.
        const int b = m0 / SEQ;
        const int sbase = m0 % SEQ;
#pragma unroll
        for (int i = 0; i < 2; i++)
#pragma unroll
            for (int j = 0; j < 4; j++) {
                int s = sbase + wm * 32 + i * 16;
                int gn = n0 + wn * 64 + j * 16;
                int h = gn >> 6;
                int d = gn & 63;
                float* p = Y + ((size_t)(b * NUM_HEADS + h) * SEQ + s) * HEAD_DIM + d;
                wmma::store_matrix_sync(p, c[i][j], HEAD_DIM, wmma::mem_row_major);
            }
    } else {
#pragma unroll
        for (int i = 0; i < 2; i++)
#pragma unroll
            for (int j = 0; j < 4; j++) {
                float* p = Y + (size_t)(m0 + wm * 32 + i * 16) * D_MODEL
                             + n0 + wn * 64 + j * 16;
                wmma::store_matrix_sync(p, c[i][j], D_MODEL, wmma::mem_row_major);
            }
    }
}

// ---------------------------------------------------------------------------
// Fused causal flash attention. Q staged once in smem; K/V staged per block
// via cp.async. One CTA = 64 query rows of one (b,h). grid = (S/64, B*H).
// ---------------------------------------------------------------------------
#define BQ 64
#define SP 68   // padded row stride; 68*4=272B (16B-aligned rows)
#define ATTN_SMEM_BYTES (5 * BQ * SP * 4)   // 87040

__global__ void __launch_bounds__(256)
attn_kernel()
{
    extern __shared__ float sm[];
    float* Qs = sm;                 // [BQ][SP]
    float* Ks = Qs + BQ * SP;       // [64 keys][SP] (dim along row)
    float* Vs = Ks + BQ * SP;       // [64 keys][SP]
    float* Ss = Vs + BQ * SP;       // scores / probs / PV staging
    float* Os = Ss + BQ * SP;       // output accumulator
    __shared__ float m_s[BQ], l_s[BQ], corr_s[BQ];

    const int qb = gridDim.x - 1 - blockIdx.x;   // long CTAs first
    const int bh = blockIdx.y;
    const float* Q = g_q + (size_t)bh * SEQ * HEAD_DIM;
    const float* K = g_k + (size_t)bh * SEQ * HEAD_DIM;
    const float* V = g_v + (size_t)bh * SEQ * HEAD_DIM;
    const int q0 = qb * BQ;

    const int tid  = threadIdx.x;
    const int warp = tid >> 5;
    const int wm = warp & 3;   // 16 score-rows / warp
    const int wn = warp >> 2;  // 32 score-cols / warp
    const int r  = tid >> 2;   // softmax row (0..63)
    const int cq = tid & 3;    // quarter of row (16 cols)

    // stage Q tile (64 x 64): 1024 float4, 4 per thread
    {
#pragma unroll
        for (int j = 0; j < 4; j++) {
            int idx = tid + j * 256;
            int row = idx >> 4;
            int col = (idx & 15) * 4;
            cp_async16(Qs + row * SP + col,
                       Q + (size_t)(q0 + row) * HEAD_DIM + col);
        }
        cp_commit();
    }

    if (tid < BQ) { m_s[tid] = -INFINITY; l_s[tid] = 0.0f; }
    for (int i = tid; i < BQ * SP; i += 256) Os[i] = 0.0f;

    for (int kb = 0; kb <= qb; kb++) {
        // stage K,V tiles for this block
#pragma unroll
        for (int j = 0; j < 4; j++) {
            int idx = tid + j * 256;
            int row = idx >> 4;
            int col = (idx & 15) * 4;
            cp_async16(Ks + row * SP + col,
                       K + (size_t)(kb * 64 + row) * HEAD_DIM + col);
            cp_async16(Vs + row * SP + col,
                       V + (size_t)(kb * 64 + row) * HEAD_DIM + col);
        }
        cp_commit();
        cp_wait0();
        __syncthreads();

        // ---- S = Q @ K^T ----
        {
            wmma::fragment<wmma::accumulator, 16, 16, 8, float> cs[2];
#pragma unroll
            for (int j = 0; j < 2; j++) wmma::fill_fragment(cs[j], 0.0f);
#pragma unroll
            for (int kk = 0; kk < HEAD_DIM; kk += 8) {
                wmma::fragment<wmma::matrix_a, 16, 16, 8, wmma::precision::tf32, wmma::row_major> a;
                wmma::load_matrix_sync(a, Qs + (wm * 16) * SP + kk, SP);
                frag_to_tf32(a);
#pragma unroll
                for (int j = 0; j < 2; j++) {
                    wmma::fragment<wmma::matrix_b, 16, 16, 8, wmma::precision::tf32, wmma::col_major> b;
                    wmma::load_matrix_sync(b, Ks + (wn * 32 + j * 16) * SP + kk, SP);
                    frag_to_tf32(b);
                    wmma::mma_sync(cs[j], a, b, cs[j]);
                }
            }
#pragma unroll
            for (int j = 0; j < 2; j++)
                wmma::store_matrix_sync(Ss + (wm * 16) * SP + wn * 32 + j * 16,
                                        cs[j], SP, wmma::mem_row_major);
        }
        __syncthreads();

        // ---- online softmax over this 64-wide key block ----
        {
            const int qi = q0 + r;
            const bool diag = (kb == qb);
            float xv[16];
            float mx = -INFINITY;
#pragma unroll
            for (int t = 0; t < 16; t++) {
                int cidx = cq * 16 + t;
                float x = Ss[r * SP + cidx] * 0.125f;   // 1/sqrt(64)
                if (diag && (kb * 64 + cidx > qi)) x = -INFINITY;
                xv[t] = x;
                mx = fmaxf(mx, x);
            }
            mx = fmaxf(mx, __shfl_xor_sync(0xFFFFFFFFu, mx, 1));
            mx = fmaxf(mx, __shfl_xor_sync(0xFFFFFFFFu, mx, 2));
            const float mold = m_s[r];
            const float mnew = fmaxf(mold, mx);
            float sum = 0.0f;
#pragma unroll
            for (int t = 0; t < 16; t++) {
                float p = __expf(xv[t] - mnew);
                Ss[r * SP + cq * 16 + t] = p;
                sum += p;
            }
            sum += __shfl_xor_sync(0xFFFFFFFFu, sum, 1);
            sum += __shfl_xor_sync(0xFFFFFFFFu, sum, 2);
            if (cq == 0) {
                float corr = __expf(mold - mnew);
                corr_s[r] = corr;
                m_s[r]    = mnew;
                l_s[r]    = l_s[r] * corr + sum;
            }
        }
        __syncthreads();

        // ---- PV: tile = P @ V ----
        {
            wmma::fragment<wmma::accumulator, 16, 16, 8, float> co[2];
#pragma unroll
            for (int j = 0; j < 2; j++) wmma::fill_fragment(co[j], 0.0f);
#pragma unroll
            for (int kk = 0; kk < 64; kk += 8) {
                wmma::fragment<wmma::matrix_a, 16, 16, 8, wmma::precision::tf32, wmma::row_major> a;
                wmma::load_matrix_sync(a, Ss + (wm * 16) * SP + kk, SP);
                frag_to_tf32(a);
#pragma unroll
                for (int j = 0; j < 2; j++) {
                    wmma::fragment<wmma::matrix_b, 16, 16, 8, wmma::precision::tf32, wmma::row_major> b;
                    wmma::load_matrix_sync(b, Vs + kk * SP + wn * 32 + j * 16, SP);
                    frag_to_tf32(b);
                    wmma::mma_sync(co[j], a, b, co[j]);
                }
            }
            __syncthreads();  // all warps done reading P (and V) before overwrite
#pragma unroll
            for (int j = 0; j < 2; j++)
                wmma::store_matrix_sync(Ss + (wm * 16) * SP + wn * 32 + j * 16,
                                        co[j], SP, wmma::mem_row_major);
        }
        __syncthreads();

        // ---- rescale + accumulate into Os ----
        {
            const float corr = corr_s[r];
#pragma unroll
            for (int t = 0; t < 16; t++) {
                int cidx = cq * 16 + t;
                Os[r * SP + cidx] = Os[r * SP + cidx] * corr + Ss[r * SP + cidx];
            }
        }
        __syncthreads();
    }

    // ---- finalize: ctx[b, s, h*64 + d] = Os / l ----
    {
        const float inv_l = 1.0f / l_s[r];
        const int b = bh / NUM_HEADS;
        const int h = bh % NUM_HEADS;
        float* outp = g_ctx + ((size_t)(b * SEQ + q0 + r)) * D_MODEL + h * HEAD_DIM;
#pragma unroll
        for (int t = 0; t < 16; t++) {
            int cidx = cq * 16 + t;
            outp[cidx] = Os[r * SP + cidx] * inv_l;
        }
    }
}

// ---------------------------------------------------------------------------
// bias add: out[m,n] += b[n]
// ---------------------------------------------------------------------------
__global__ void __launch_bounds__(256)
bias_kernel(float* __restrict__ out, const float* __restrict__ bias)
{
    int i = blockIdx.x * 256 + threadIdx.x;
    out[i] += bias[i & (D_MODEL - 1)];
}

// ---------------------------------------------------------------------------
// launch (no static guards — set attributes unconditionally; host-side,
// non-stream API, graph-capture transparent)
// ---------------------------------------------------------------------------
extern "C" void kernel_launch(void* const* d_in, const int* in_sizes, int n_in,
                              void* d_out, int out_size)
{
    const float* x  = (const float*)d_in[0];
    const float* wq = (const float*)d_in[1];
    const float* wk = (const float*)d_in[2];
    const float* wv = (const float*)d_in[3];
    const float* wo = (const float*)d_in[4];
    const float* bo = (const float*)d_in[5];
    float* out = (float*)d_out;

    cudaFuncSetAttribute(gemm_tf32_db<0>,
                         cudaFuncAttributeMaxDynamicSharedMemorySize, GEMM_SMEM_BYTES);
    cudaFuncSetAttribute(gemm_tf32_db<1>,
                         cudaFuncAttributeMaxDynamicSharedMemorySize, GEMM_SMEM_BYTES);
    cudaFuncSetAttribute(attn_kernel,
                         cudaFuncAttributeMaxDynamicSharedMemorySize, ATTN_SMEM_BYTES);

    // QKV projections: grid (N/BN, M/BM, 3)
    dim3 gqkv(D_MODEL / BN, M_TOTAL / BM, 3);
    gemm_tf32_db<0><<<gqkv, 256, GEMM_SMEM_BYTES>>>(x, wq, wk, wv, nullptr);

    // fused causal attention
    dim3 gattn(SEQ / BQ, BATCH * NUM_HEADS);
    attn_kernel<<<gattn, 256, ATTN_SMEM_BYTES>>>();

    // out projection
    dim3 gout(D_MODEL / BN, M_TOTAL / BM, 1);
    gemm_tf32_db<1><<<gout, 256, GEMM_SMEM_BYTES>>>(nullptr, wo, nullptr, nullptr, out);

    // bias
    bias_kernel<<<(M_TOTAL * D_MODEL) / 256, 256>>>(out, bo);
}

// round 6
// speedup vs baseline: 4.5290x; 3.1398x over previous
#include <cuda_runtime.h>
#include <cuda_fp16.h>
#include <cstdint>
#include <mma.h>
#include <math.h>

using namespace nvcuda;

// Problem constants
#define D_MODEL   1024
#define NUM_HEADS 16
#define HEAD_DIM  64
#define SEQ       2048
#define BATCH     2
#define M_TOTAL   (BATCH * SEQ)   // 4096

// Scratch (no allocation allowed -> __device__ globals)
__device__ __half g_xh[M_TOTAL * D_MODEL];
__device__ __half g_wqh[D_MODEL * D_MODEL];
__device__ __half g_wkh[D_MODEL * D_MODEL];
__device__ __half g_wvh[D_MODEL * D_MODEL];
__device__ __half g_woh[D_MODEL * D_MODEL];
__device__ __half g_q[BATCH * NUM_HEADS * SEQ * HEAD_DIM];   // [B,H,S,Dh]
__device__ __half g_k[BATCH * NUM_HEADS * SEQ * HEAD_DIM];
__device__ __half g_v[BATCH * NUM_HEADS * SEQ * HEAD_DIM];
__device__ __half g_ctx[M_TOTAL * D_MODEL];                  // [B,S,D]

// ---------------------------------------------------------------------------
// helpers
// ---------------------------------------------------------------------------
__device__ __forceinline__ void cp_async16(void* smem_ptr, const void* gmem_ptr) {
    unsigned int s = (unsigned int)__cvta_generic_to_shared(smem_ptr);
    asm volatile("cp.async.cg.shared.global [%0], [%1], 16;\n" :: "r"(s), "l"(gmem_ptr));
}
__device__ __forceinline__ void cp_commit() { asm volatile("cp.async.commit_group;\n"); }
__device__ __forceinline__ void cp_wait0()  { asm volatile("cp.async.wait_group 0;\n"); }
__device__ __forceinline__ void cp_wait1()  { asm volatile("cp.async.wait_group 1;\n"); }

// ---------------------------------------------------------------------------
// float -> half conversion (one-time, DRAM streaming)
// ---------------------------------------------------------------------------
__global__ void __launch_bounds__(256)
f2h_kernel(const float* __restrict__ src, __half* __restrict__ dst)
{
    int i = (blockIdx.x * 256 + threadIdx.x) * 4;
    float4 v = *reinterpret_cast<const float4*>(src + i);
    *reinterpret_cast<__half2*>(dst + i)     = __floats2half2_rn(v.x, v.y);
    *reinterpret_cast<__half2*>(dst + i + 2) = __floats2half2_rn(v.z, v.w);
}

// ---------------------------------------------------------------------------
// fp16 GEMM:  Y = X @ W^T   (X: [M,K] rm half, W: [N,K] rm half)
// 128x128x64 tiles, double-buffered cp.async, m16n16k16 wmma, fp32 accum.
// MODE 0: QKV -> g_q/g_k/g_v (half, [B,H,S,Dh]).  MODE 1: out proj + bias -> float.
// ---------------------------------------------------------------------------
#define BKH 64
#define HS  72   // padded half stride (multiple of 8; 144B rows)
#define GEMM_SMEM (2 * 2 * 128 * HS * 2)   // 73728 B (>= 128*128*4 for epilogue stage)

template <int MODE>
__global__ void __launch_bounds__(256)
gemm_h(float* __restrict__ Yout, const float* __restrict__ bias)
{
    extern __shared__ __align__(16) char smraw[];
    __half* sm_h = (__half*)smraw;
    float*  sm_f = (float*)smraw;

    const __half* Xp;
    const __half* W;
    __half* Yh = nullptr;
    if (MODE == 0) {
        int which = blockIdx.z;
        W  = (which == 0) ? g_wqh : (which == 1) ? g_wkh : g_wvh;
        Yh = (which == 0) ? g_q   : (which == 1) ? g_k   : g_v;
        Xp = g_xh;
    } else {
        W  = g_woh;
        Xp = g_ctx;
    }

    const int m0 = blockIdx.y * 128;
    const int n0 = blockIdx.x * 128;
    const int tid  = threadIdx.x;
    const int warp = tid >> 5;
    const int wm = warp >> 1;   // 0..3 : 32 rows
    const int wn = warp & 1;    // 0..1 : 64 cols

    wmma::fragment<wmma::accumulator, 16, 16, 16, float> c[2][4];
#pragma unroll
    for (int i = 0; i < 2; i++)
#pragma unroll
        for (int j = 0; j < 4; j++)
            wmma::fill_fragment(c[i][j], 0.0f);

    const int NIT = D_MODEL / BKH;   // 16

    auto load_stage = [&](int kblk, int s) {
        const int k0 = kblk * BKH;
        __half* Ab = sm_h + s * (2 * 128 * HS);
        __half* Bb = Ab + 128 * HS;
#pragma unroll
        for (int j = 0; j < 4; j++) {
            int idx = tid + j * 256;     // 0..1023
            int row = idx >> 3;          // 0..127
            int ch  = idx & 7;           // 16B chunk (8 halves)
            cp_async16(Ab + row * HS + ch * 8,
                       Xp + (size_t)(m0 + row) * D_MODEL + k0 + ch * 8);
            cp_async16(Bb + row * HS + ch * 8,
                       W  + (size_t)(n0 + row) * D_MODEL + k0 + ch * 8);
        }
        cp_commit();
    };

    load_stage(0, 0);

    for (int it = 0; it < NIT; it++) {
        const int buf = it & 1;
        if (it + 1 < NIT) { load_stage(it + 1, buf ^ 1); cp_wait1(); }
        else              { cp_wait0(); }
        __syncthreads();

        const __half* Ab = sm_h + buf * (2 * 128 * HS);
        const __half* Bb = Ab + 128 * HS;
#pragma unroll
        for (int kk = 0; kk < BKH; kk += 16) {
            wmma::fragment<wmma::matrix_a, 16, 16, 16, __half, wmma::row_major> a[2];
            wmma::fragment<wmma::matrix_b, 16, 16, 16, __half, wmma::col_major> b[4];
#pragma unroll
            for (int i = 0; i < 2; i++)
                wmma::load_matrix_sync(a[i], Ab + (wm * 32 + i * 16) * HS + kk, HS);
#pragma unroll
            for (int j = 0; j < 4; j++)
                wmma::load_matrix_sync(b[j], Bb + (wn * 64 + j * 16) * HS + kk, HS);
#pragma unroll
            for (int i = 0; i < 2; i++)
#pragma unroll
                for (int j = 0; j < 4; j++)
                    wmma::mma_sync(c[i][j], a[i], b[j], c[i][j]);
        }
        __syncthreads();
    }

    // epilogue: stage fp32 result tile in smem, then convert/write out
#pragma unroll
    for (int i = 0; i < 2; i++)
#pragma unroll
        for (int j = 0; j < 4; j++)
            wmma::store_matrix_sync(sm_f + (wm * 32 + i * 16) * 128 + wn * 64 + j * 16,
                                    c[i][j], 128, wmma::mem_row_major);
    __syncthreads();

#pragma unroll
    for (int t = 0; t < 16; t++) {
        int idx = tid + t * 256;           // 0..4095 float4s
        int row = idx >> 5;                // 0..127
        int c4  = (idx & 31) * 4;          // 0..124
        float4 v = *reinterpret_cast<const float4*>(sm_f + row * 128 + c4);
        const int m = m0 + row;
        const int n = n0 + c4;
        if (MODE == 0) {
            const int b = m >> 11;
            const int s = m & 2047;
            const int h = n >> 6;
            const int d = n & 63;
            __half* dst = Yh + ((size_t)(b * NUM_HEADS + h) * SEQ + s) * HEAD_DIM + d;
            *reinterpret_cast<__half2*>(dst)     = __floats2half2_rn(v.x, v.y);
            *reinterpret_cast<__half2*>(dst + 2) = __floats2half2_rn(v.z, v.w);
        } else {
            float4 bb = *reinterpret_cast<const float4*>(bias + n);
            float4 o = make_float4(v.x + bb.x, v.y + bb.y, v.z + bb.z, v.w + bb.w);
            *reinterpret_cast<float4*>(Yout + (size_t)m * D_MODEL + n) = o;
        }
    }
}

// ---------------------------------------------------------------------------
// Fused causal flash attention, fp16 operands / fp32 state.
// Q staged once; K/V double-buffered cp.async prefetch.
// One CTA = 64 query rows of one (b,h). grid = (S/64, B*H).
// ---------------------------------------------------------------------------
#define BQ 64
#define SPF 68   // float stride for Ss/Os
// smem layout (bytes):
//   Qs  h[64][72]        @ 0       (9216)
//   Ks  h[2][64][72]     @ 9216    (18432)
//   Vs  h[2][64][72]     @ 27648   (18432)
//   Ps  h[64][72]        @ 46080   (9216)
//   Ss  f[64][68]        @ 55296   (17408)
//   Os  f[64][68]        @ 72704   (17408)
#define ATTN_SMEM 90112

__global__ void __launch_bounds__(256)
attn_kernel()
{
    extern __shared__ __align__(16) char smraw[];
    __half* Qs = (__half*)smraw;
    __half* Ks = (__half*)(smraw + 9216);
    __half* Vs = (__half*)(smraw + 27648);
    __half* Ps = (__half*)(smraw + 46080);
    float*  Ss = (float*)(smraw + 55296);
    float*  Os = (float*)(smraw + 72704);
    __shared__ float m_s[BQ], l_s[BQ], corr_s[BQ];

    const int qb = gridDim.x - 1 - blockIdx.x;   // long CTAs first
    const int bh = blockIdx.y;
    const __half* Q = g_q + (size_t)bh * SEQ * HEAD_DIM;
    const __half* K = g_k + (size_t)bh * SEQ * HEAD_DIM;
    const __half* V = g_v + (size_t)bh * SEQ * HEAD_DIM;
    const int q0 = qb * BQ;

    const int tid  = threadIdx.x;
    const int warp = tid >> 5;
    const int wm = warp & 3;   // 16 score-rows / warp
    const int wn = warp >> 2;  // 32 score-cols / warp
    const int r  = tid >> 2;   // softmax row
    const int cq = tid & 3;    // quarter of row

    // KV tile loader: 64 rows x 64 halves = 512 16B chunks, 2/thread each of K,V
    auto load_kv = [&](int kb, int s) {
        __half* Kb = Ks + s * 64 * HS;
        __half* Vb = Vs + s * 64 * HS;
#pragma unroll
        for (int j = 0; j < 2; j++) {
            int idx = tid + j * 256;   // 0..511
            int row = idx >> 3;        // 0..63
            int ch  = idx & 7;
            cp_async16(Kb + row * HS + ch * 8, K + (size_t)(kb * 64 + row) * HEAD_DIM + ch * 8);
            cp_async16(Vb + row * HS + ch * 8, V + (size_t)(kb * 64 + row) * HEAD_DIM + ch * 8);
        }
        cp_commit();
    };

    // stage Q (group), then KV block 0 (group)
    {
#pragma unroll
        for (int j = 0; j < 2; j++) {
            int idx = tid + j * 256;
            int row = idx >> 3;
            int ch  = idx & 7;
            cp_async16(Qs + row * HS + ch * 8, Q + (size_t)(q0 + row) * HEAD_DIM + ch * 8);
        }
        cp_commit();
    }
    load_kv(0, 0);

    if (tid < BQ) { m_s[tid] = -INFINITY; l_s[tid] = 0.0f; }
    for (int i = tid; i < BQ * SPF; i += 256) Os[i] = 0.0f;

    for (int kb = 0; kb <= qb; kb++) {
        const int buf = kb & 1;
        if (kb < qb) { load_kv(kb + 1, buf ^ 1); cp_wait1(); }
        else         { cp_wait0(); }
        __syncthreads();

        const __half* Kb = Ks + buf * 64 * HS;
        const __half* Vb = Vs + buf * 64 * HS;

        // ---- S = Q @ K^T ----
        {
            wmma::fragment<wmma::accumulator, 16, 16, 16, float> cs[2];
#pragma unroll
            for (int j = 0; j < 2; j++) wmma::fill_fragment(cs[j], 0.0f);
#pragma unroll
            for (int kk = 0; kk < HEAD_DIM; kk += 16) {
                wmma::fragment<wmma::matrix_a, 16, 16, 16, __half, wmma::row_major> a;
                wmma::load_matrix_sync(a, Qs + (wm * 16) * HS + kk, HS);
#pragma unroll
                for (int j = 0; j < 2; j++) {
                    wmma::fragment<wmma::matrix_b, 16, 16, 16, __half, wmma::col_major> b;
                    wmma::load_matrix_sync(b, Kb + (wn * 32 + j * 16) * HS + kk, HS);
                    wmma::mma_sync(cs[j], a, b, cs[j]);
                }
            }
#pragma unroll
            for (int j = 0; j < 2; j++)
                wmma::store_matrix_sync(Ss + (wm * 16) * SPF + wn * 32 + j * 16,
                                        cs[j], SPF, wmma::mem_row_major);
        }
        __syncthreads();

        // ---- online softmax; P -> half ----
        {
            const int qi = q0 + r;
            const bool diag = (kb == qb);
            float xv[16];
            float mx = -INFINITY;
#pragma unroll
            for (int t = 0; t < 16; t++) {
                int cidx = cq * 16 + t;
                float x = Ss[r * SPF + cidx] * 0.125f;   // 1/sqrt(64)
                if (diag && (kb * 64 + cidx > qi)) x = -INFINITY;
                xv[t] = x;
                mx = fmaxf(mx, x);
            }
            mx = fmaxf(mx, __shfl_xor_sync(0xFFFFFFFFu, mx, 1));
            mx = fmaxf(mx, __shfl_xor_sync(0xFFFFFFFFu, mx, 2));
            const float mold = m_s[r];
            const float mnew = fmaxf(mold, mx);
            float sum = 0.0f;
#pragma unroll
            for (int t = 0; t < 16; t += 2) {
                float p0 = __expf(xv[t]     - mnew);
                float p1 = __expf(xv[t + 1] - mnew);
                *reinterpret_cast<__half2*>(Ps + r * HS + cq * 16 + t) = __floats2half2_rn(p0, p1);
                sum += p0 + p1;
            }
            sum += __shfl_xor_sync(0xFFFFFFFFu, sum, 1);
            sum += __shfl_xor_sync(0xFFFFFFFFu, sum, 2);
            if (cq == 0) {
                float corr = __expf(mold - mnew);
                corr_s[r] = corr;
                m_s[r]    = mnew;
                l_s[r]    = l_s[r] * corr + sum;
            }
        }
        __syncthreads();

        // ---- PV: tile = P @ V ----
        {
            wmma::fragment<wmma::accumulator, 16, 16, 16, float> co[2];
#pragma unroll
            for (int j = 0; j < 2; j++) wmma::fill_fragment(co[j], 0.0f);
#pragma unroll
            for (int kk = 0; kk < 64; kk += 16) {
                wmma::fragment<wmma::matrix_a, 16, 16, 16, __half, wmma::row_major> a;
                wmma::load_matrix_sync(a, Ps + (wm * 16) * HS + kk, HS);
#pragma unroll
                for (int j = 0; j < 2; j++) {
                    wmma::fragment<wmma::matrix_b, 16, 16, 16, __half, wmma::row_major> b;
                    wmma::load_matrix_sync(b, Vb + kk * HS + wn * 32 + j * 16, HS);
                    wmma::mma_sync(co[j], a, b, co[j]);
                }
            }
            // Ss reads (softmax) finished at previous barrier; P lives in Ps, so
            // overwriting Ss here is safe without an extra barrier.
#pragma unroll
            for (int j = 0; j < 2; j++)
                wmma::store_matrix_sync(Ss + (wm * 16) * SPF + wn * 32 + j * 16,
                                        co[j], SPF, wmma::mem_row_major);
        }
        __syncthreads();

        // ---- rescale + accumulate into Os ----
        {
            const float corr = corr_s[r];
#pragma unroll
            for (int t = 0; t < 16; t++) {
                int cidx = cq * 16 + t;
                Os[r * SPF + cidx] = Os[r * SPF + cidx] * corr + Ss[r * SPF + cidx];
            }
        }
        __syncthreads();
    }

    // ---- finalize: ctx (half) ----
    {
        const float inv_l = 1.0f / l_s[r];
        const int b = bh / NUM_HEADS;
        const int h = bh % NUM_HEADS;
        __half* outp = g_ctx + ((size_t)(b * SEQ + q0 + r)) * D_MODEL + h * HEAD_DIM;
#pragma unroll
        for (int t = 0; t < 16; t += 2) {
            int cidx = cq * 16 + t;
            *reinterpret_cast<__half2*>(outp + cidx) =
                __floats2half2_rn(Os[r * SPF + cidx] * inv_l, Os[r * SPF + cidx + 1] * inv_l);
        }
    }
}

// ---------------------------------------------------------------------------
// launch
// ---------------------------------------------------------------------------
extern "C" void kernel_launch(void* const* d_in, const int* in_sizes, int n_in,
                              void* d_out, int out_size)
{
    const float* x  = (const float*)d_in[0];
    const float* wq = (const float*)d_in[1];
    const float* wk = (const float*)d_in[2];
    const float* wv = (const float*)d_in[3];
    const float* wo = (const float*)d_in[4];
    const float* bo = (const float*)d_in[5];
    float* out = (float*)d_out;

    cudaFuncSetAttribute(gemm_h<0>, cudaFuncAttributeMaxDynamicSharedMemorySize, GEMM_SMEM);
    cudaFuncSetAttribute(gemm_h<1>, cudaFuncAttributeMaxDynamicSharedMemorySize, GEMM_SMEM);
    cudaFuncSetAttribute(attn_kernel, cudaFuncAttributeMaxDynamicSharedMemorySize, ATTN_SMEM);

    // device-global symbol addresses (host side)
    __half *xh, *wqh, *wkh, *wvh, *woh;
    cudaGetSymbolAddress((void**)&xh,  g_xh);
    cudaGetSymbolAddress((void**)&wqh, g_wqh);
    cudaGetSymbolAddress((void**)&wkh, g_wkh);
    cudaGetSymbolAddress((void**)&wvh, g_wvh);
    cudaGetSymbolAddress((void**)&woh, g_woh);

    // fp32 -> fp16 converts
    f2h_kernel<<<(M_TOTAL * D_MODEL) / 1024, 256>>>(x,  xh);
    f2h_kernel<<<(D_MODEL * D_MODEL) / 1024, 256>>>(wq, wqh);
    f2h_kernel<<<(D_MODEL * D_MODEL) / 1024, 256>>>(wk, wkh);
    f2h_kernel<<<(D_MODEL * D_MODEL) / 1024, 256>>>(wv, wvh);
    f2h_kernel<<<(D_MODEL * D_MODEL) / 1024, 256>>>(wo, woh);

    // QKV projections: grid (N/128, M/128, 3)
    dim3 gqkv(D_MODEL / 128, M_TOTAL / 128, 3);
    gemm_h<0><<<gqkv, 256, GEMM_SMEM>>>(nullptr, nullptr);

    // fused causal attention
    dim3 gattn(SEQ / BQ, BATCH * NUM_HEADS);
    attn_kernel<<<gattn, 256, ATTN_SMEM>>>();

    // out projection + bias
    dim3 gout(D_MODEL / 128, M_TOTAL / 128, 1);
    gemm_h<1><<<gout, 256, GEMM_SMEM>>>(out, bo);
}

// round 7
// speedup vs baseline: 4.6712x; 1.0314x over previous
#include <cuda_runtime.h>
#include <cuda_fp16.h>
#include <cstdint>
#include <mma.h>
#include <math.h>

using namespace nvcuda;

// Problem constants
#define D_MODEL   1024
#define NUM_HEADS 16
#define HEAD_DIM  64
#define SEQ       2048
#define BATCH     2
#define M_TOTAL   (BATCH * SEQ)   // 4096

// Scratch (no allocation allowed -> __device__ globals)
__device__ __half g_xh[M_TOTAL * D_MODEL];
__device__ __half g_wqh[D_MODEL * D_MODEL];
__device__ __half g_wkh[D_MODEL * D_MODEL];
__device__ __half g_wvh[D_MODEL * D_MODEL];
__device__ __half g_woh[D_MODEL * D_MODEL];
__device__ __half g_q[BATCH * NUM_HEADS * SEQ * HEAD_DIM];   // [B,H,S,Dh]
__device__ __half g_k[BATCH * NUM_HEADS * SEQ * HEAD_DIM];
__device__ __half g_v[BATCH * NUM_HEADS * SEQ * HEAD_DIM];
__device__ __half g_ctx[M_TOTAL * D_MODEL];                  // [B,S,D]

// ---------------------------------------------------------------------------
// helpers
// ---------------------------------------------------------------------------
__device__ __forceinline__ void cp_async16(void* smem_ptr, const void* gmem_ptr) {
    unsigned int s = (unsigned int)__cvta_generic_to_shared(smem_ptr);
    asm volatile("cp.async.cg.shared.global [%0], [%1], 16;\n" :: "r"(s), "l"(gmem_ptr));
}
__device__ __forceinline__ void cp_commit() { asm volatile("cp.async.commit_group;\n"); }
__device__ __forceinline__ void cp_wait0()  { asm volatile("cp.async.wait_group 0;\n"); }
__device__ __forceinline__ void cp_wait1()  { asm volatile("cp.async.wait_group 1;\n"); }

// ---------------------------------------------------------------------------
// float -> half conversion (one-time, DRAM streaming)
// ---------------------------------------------------------------------------
__global__ void __launch_bounds__(256)
f2h_kernel(const float* __restrict__ src, __half* __restrict__ dst)
{
    int i = (blockIdx.x * 256 + threadIdx.x) * 4;
    float4 v = *reinterpret_cast<const float4*>(src + i);
    *reinterpret_cast<__half2*>(dst + i)     = __floats2half2_rn(v.x, v.y);
    *reinterpret_cast<__half2*>(dst + i + 2) = __floats2half2_rn(v.z, v.w);
}

// ---------------------------------------------------------------------------
// fp16 GEMM (unchanged from R6):  Y = X @ W^T
// 128x128x64 tiles, double-buffered cp.async, m16n16k16 wmma, fp32 accum.
// ---------------------------------------------------------------------------
#define BKH 64
#define HS  72   // padded half stride
#define GEMM_SMEM (2 * 2 * 128 * HS * 2)   // 73728 B

template <int MODE>
__global__ void __launch_bounds__(256)
gemm_h(float* __restrict__ Yout, const float* __restrict__ bias)
{
    extern __shared__ __align__(16) char smraw[];
    __half* sm_h = (__half*)smraw;
    float*  sm_f = (float*)smraw;

    const __half* Xp;
    const __half* W;
    __half* Yh = nullptr;
    if (MODE == 0) {
        int which = blockIdx.z;
        W  = (which == 0) ? g_wqh : (which == 1) ? g_wkh : g_wvh;
        Yh = (which == 0) ? g_q   : (which == 1) ? g_k   : g_v;
        Xp = g_xh;
    } else {
        W  = g_woh;
        Xp = g_ctx;
    }

    const int m0 = blockIdx.y * 128;
    const int n0 = blockIdx.x * 128;
    const int tid  = threadIdx.x;
    const int warp = tid >> 5;
    const int wm = warp >> 1;
    const int wn = warp & 1;

    wmma::fragment<wmma::accumulator, 16, 16, 16, float> c[2][4];
#pragma unroll
    for (int i = 0; i < 2; i++)
#pragma unroll
        for (int j = 0; j < 4; j++)
            wmma::fill_fragment(c[i][j], 0.0f);

    const int NIT = D_MODEL / BKH;   // 16

    auto load_stage = [&](int kblk, int s) {
        const int k0 = kblk * BKH;
        __half* Ab = sm_h + s * (2 * 128 * HS);
        __half* Bb = Ab + 128 * HS;
#pragma unroll
        for (int j = 0; j < 4; j++) {
            int idx = tid + j * 256;
            int row = idx >> 3;
            int ch  = idx & 7;
            cp_async16(Ab + row * HS + ch * 8,
                       Xp + (size_t)(m0 + row) * D_MODEL + k0 + ch * 8);
            cp_async16(Bb + row * HS + ch * 8,
                       W  + (size_t)(n0 + row) * D_MODEL + k0 + ch * 8);
        }
        cp_commit();
    };

    load_stage(0, 0);

    for (int it = 0; it < NIT; it++) {
        const int buf = it & 1;
        if (it + 1 < NIT) { load_stage(it + 1, buf ^ 1); cp_wait1(); }
        else              { cp_wait0(); }
        __syncthreads();

        const __half* Ab = sm_h + buf * (2 * 128 * HS);
        const __half* Bb = Ab + 128 * HS;
#pragma unroll
        for (int kk = 0; kk < BKH; kk += 16) {
            wmma::fragment<wmma::matrix_a, 16, 16, 16, __half, wmma::row_major> a[2];
            wmma::fragment<wmma::matrix_b, 16, 16, 16, __half, wmma::col_major> b[4];
#pragma unroll
            for (int i = 0; i < 2; i++)
                wmma::load_matrix_sync(a[i], Ab + (wm * 32 + i * 16) * HS + kk, HS);
#pragma unroll
            for (int j = 0; j < 4; j++)
                wmma::load_matrix_sync(b[j], Bb + (wn * 64 + j * 16) * HS + kk, HS);
#pragma unroll
            for (int i = 0; i < 2; i++)
#pragma unroll
                for (int j = 0; j < 4; j++)
                    wmma::mma_sync(c[i][j], a[i], b[j], c[i][j]);
        }
        __syncthreads();
    }

#pragma unroll
    for (int i = 0; i < 2; i++)
#pragma unroll
        for (int j = 0; j < 4; j++)
            wmma::store_matrix_sync(sm_f + (wm * 32 + i * 16) * 128 + wn * 64 + j * 16,
                                    c[i][j], 128, wmma::mem_row_major);
    __syncthreads();

#pragma unroll
    for (int t = 0; t < 16; t++) {
        int idx = tid + t * 256;
        int row = idx >> 5;
        int c4  = (idx & 31) * 4;
        float4 v = *reinterpret_cast<const float4*>(sm_f + row * 128 + c4);
        const int m = m0 + row;
        const int n = n0 + c4;
        if (MODE == 0) {
            const int b = m >> 11;
            const int s = m & 2047;
            const int h = n >> 6;
            const int d = n & 63;
            __half* dst = Yh + ((size_t)(b * NUM_HEADS + h) * SEQ + s) * HEAD_DIM + d;
            *reinterpret_cast<__half2*>(dst)     = __floats2half2_rn(v.x, v.y);
            *reinterpret_cast<__half2*>(dst + 2) = __floats2half2_rn(v.z, v.w);
        } else {
            float4 bb = *reinterpret_cast<const float4*>(bias + n);
            float4 o = make_float4(v.x + bb.x, v.y + bb.y, v.z + bb.z, v.w + bb.w);
            *reinterpret_cast<float4*>(Yout + (size_t)m * D_MODEL + n) = o;
        }
    }
}

// ---------------------------------------------------------------------------
// Fused causal flash attention v2 — warp-private softmax.
// 128 threads / 4 warps; each warp owns 16 query rows x 64 keys.
// One __syncthreads per key block (KV double-buffer gate); everything else
// is intra-warp. Q fragments register-resident across all key blocks.
// grid = (S/64, B*H).
// smem layout (bytes):
//   Qs h[64][72]      @ 0      (9216)
//   Ks h[2][64][72]   @ 9216   (18432)
//   Vs h[2][64][72]   @ 27648  (18432)
//   Ss f[4][16][72]   @ 46080  (18432)   per-warp S / PV staging
//   Ps h[4][16][72]   @ 64512  (9216)    per-warp P
//   Os f[64][72]      @ 73728  (18432)
#define ATTN_SMEM 92160

__global__ void __launch_bounds__(128)
attn_kernel()
{
    extern __shared__ __align__(16) char smraw[];
    __half* Qs = (__half*)smraw;
    __half* Ks = (__half*)(smraw + 9216);
    __half* Vs = (__half*)(smraw + 27648);
    float*  Ss = (float*)(smraw + 46080);
    __half* Ps = (__half*)(smraw + 64512);
    float*  Os = (float*)(smraw + 73728);

    const int qb = gridDim.x - 1 - blockIdx.x;   // long CTAs first
    const int bh = blockIdx.y;
    const __half* Q = g_q + (size_t)bh * SEQ * HEAD_DIM;
    const __half* K = g_k + (size_t)bh * SEQ * HEAD_DIM;
    const __half* V = g_v + (size_t)bh * SEQ * HEAD_DIM;
    const int q0 = qb * 64;

    const int tid  = threadIdx.x;
    const int warp = tid >> 5;
    const int lane = tid & 31;
    const int r    = lane >> 1;       // warp-local row 0..15
    const int hsel = lane & 1;        // which 32-col half of the row

    float*  Sw = Ss + warp * 16 * 72;
    __half* Pw = Ps + warp * 16 * 72;

    // loaders (128 threads): 64 rows x 8 chunks = 512 chunks -> 4/thread
    auto load_q = [&]() {
#pragma unroll
        for (int j = 0; j < 4; j++) {
            int idx = tid + j * 128;
            int row = idx >> 3;
            int ch  = idx & 7;
            cp_async16(Qs + row * HS + ch * 8, Q + (size_t)(q0 + row) * HEAD_DIM + ch * 8);
        }
        cp_commit();
    };
    auto load_kv = [&](int kb, int s) {
        __half* Kb = Ks + s * 64 * HS;
        __half* Vb = Vs + s * 64 * HS;
#pragma unroll
        for (int j = 0; j < 4; j++) {
            int idx = tid + j * 128;
            int row = idx >> 3;
            int ch  = idx & 7;
            cp_async16(Kb + row * HS + ch * 8, K + (size_t)(kb * 64 + row) * HEAD_DIM + ch * 8);
            cp_async16(Vb + row * HS + ch * 8, V + (size_t)(kb * 64 + row) * HEAD_DIM + ch * 8);
        }
        cp_commit();
    };

    load_q();
    load_kv(0, 0);

    // zero O accumulator (64x72 floats, 1152 float4 / 128 threads = 9 each)
#pragma unroll
    for (int j = 0; j < 9; j++) {
        int idx = tid + j * 128;
        *reinterpret_cast<float4*>(Os + idx * 4) = make_float4(0.f, 0.f, 0.f, 0.f);
    }

    cp_wait0();
    __syncthreads();   // Q + KV0 resident

    // Q fragments: register-resident for the whole kernel
    wmma::fragment<wmma::matrix_a, 16, 16, 16, __half, wmma::row_major> aq[4];
#pragma unroll
    for (int kk = 0; kk < 4; kk++)
        wmma::load_matrix_sync(aq[kk], Qs + (warp * 16) * HS + kk * 16, HS);

    // per-lane row state (row r, duplicated across the 2 lanes of the pair)
    float m_i = -INFINITY, l_i = 0.0f;
    const int qi = q0 + warp * 16 + r;

    for (int kb = 0; kb <= qb; kb++) {
        const int buf = kb & 1;
        if (kb < qb) load_kv(kb + 1, buf ^ 1);   // buf^1 freed by last iter's barrier

        const __half* Kb = Ks + buf * 64 * HS;
        const __half* Vb = Vs + buf * 64 * HS;

        // ---- S = Q @ K^T (warp-private 16x64) ----
#pragma unroll
        for (int j = 0; j < 4; j++) {
            wmma::fragment<wmma::accumulator, 16, 16, 16, float> cs;
            wmma::fill_fragment(cs, 0.0f);
#pragma unroll
            for (int kk = 0; kk < 4; kk++) {
                wmma::fragment<wmma::matrix_b, 16, 16, 16, __half, wmma::col_major> b;
                wmma::load_matrix_sync(b, Kb + (j * 16) * HS + kk * 16, HS);
                wmma::mma_sync(cs, aq[kk], b, cs);
            }
            wmma::store_matrix_sync(Sw + j * 16, cs, 72, wmma::mem_row_major);
        }
        __syncwarp();

        // ---- online softmax (per-lane: row r, cols hsel*32..+31) ----
        float corr;
        {
            const bool diag = (kb == qb);
            const int kbase = kb * 64 + hsel * 32;
            const float* srow = Sw + r * 72 + hsel * 32;
            float xv[32];
            float mx = -INFINITY;
#pragma unroll
            for (int t = 0; t < 32; t++) {
                float x = srow[t] * 0.125f;   // 1/sqrt(64)
                if (diag && (kbase + t > qi)) x = -INFINITY;
                xv[t] = x;
                mx = fmaxf(mx, x);
            }
            mx = fmaxf(mx, __shfl_xor_sync(0xFFFFFFFFu, mx, 1));
            const float mnew = fmaxf(m_i, mx);
            corr = __expf(m_i - mnew);
            float sum = 0.0f;
            __half* prow = Pw + r * 72 + hsel * 32;
#pragma unroll
            for (int t = 0; t < 32; t += 2) {
                float p0 = __expf(xv[t]     - mnew);
                float p1 = __expf(xv[t + 1] - mnew);
                *reinterpret_cast<__half2*>(prow + t) = __floats2half2_rn(p0, p1);
                sum += p0 + p1;
            }
            sum += __shfl_xor_sync(0xFFFFFFFFu, sum, 1);
            l_i = l_i * corr + sum;
            m_i = mnew;
        }
        __syncwarp();

        // ---- PV: 16x64 tile = P @ V ----
#pragma unroll
        for (int j = 0; j < 4; j++) {
            wmma::fragment<wmma::accumulator, 16, 16, 16, float> co;
            wmma::fill_fragment(co, 0.0f);
#pragma unroll
            for (int kk = 0; kk < 4; kk++) {
                wmma::fragment<wmma::matrix_a, 16, 16, 16, __half, wmma::row_major> a;
                wmma::load_matrix_sync(a, Pw + kk * 16, 72);
                wmma::fragment<wmma::matrix_b, 16, 16, 16, __half, wmma::row_major> b;
                wmma::load_matrix_sync(b, Vb + (kk * 16) * HS + j * 16, HS);
                wmma::mma_sync(co, a, b, co);
            }
            wmma::store_matrix_sync(Sw + j * 16, co, 72, wmma::mem_row_major);
        }
        __syncwarp();

        // ---- O = O*corr + PV (per-lane: row r, 32 cols) ----
        {
            float* orow = Os + (warp * 16 + r) * 72 + hsel * 32;
            const float* srow = Sw + r * 72 + hsel * 32;
#pragma unroll
            for (int t = 0; t < 32; t += 4) {
                float4 o = *reinterpret_cast<float4*>(orow + t);
                float4 s = *reinterpret_cast<const float4*>(srow + t);
                o.x = o.x * corr + s.x;
                o.y = o.y * corr + s.y;
                o.z = o.z * corr + s.z;
                o.w = o.w * corr + s.w;
                *reinterpret_cast<float4*>(orow + t) = o;
            }
        }

        if (kb < qb) cp_wait0();
        __syncthreads();   // all warps done with buf; next load target is free
    }

    // ---- finalize: ctx[b, s, h*64 + d] (half) ----
    {
        const float inv_l = 1.0f / l_i;
        const int b = bh / NUM_HEADS;
        const int h = bh % NUM_HEADS;
        const int s = q0 + warp * 16 + r;
        const float* orow = Os + (warp * 16 + r) * 72 + hsel * 32;
        __half* outp = g_ctx + ((size_t)(b * SEQ + s)) * D_MODEL + h * HEAD_DIM + hsel * 32;
#pragma unroll
        for (int t = 0; t < 32; t += 2)
            *reinterpret_cast<__half2*>(outp + t) =
                __floats2half2_rn(orow[t] * inv_l, orow[t + 1] * inv_l);
    }
}

// ---------------------------------------------------------------------------
// launch
// ---------------------------------------------------------------------------
extern "C" void kernel_launch(void* const* d_in, const int* in_sizes, int n_in,
                              void* d_out, int out_size)
{
    const float* x  = (const float*)d_in[0];
    const float* wq = (const float*)d_in[1];
    const float* wk = (const float*)d_in[2];
    const float* wv = (const float*)d_in[3];
    const float* wo = (const float*)d_in[4];
    const float* bo = (const float*)d_in[5];
    float* out = (float*)d_out;

    cudaFuncSetAttribute(gemm_h<0>, cudaFuncAttributeMaxDynamicSharedMemorySize, GEMM_SMEM);
    cudaFuncSetAttribute(gemm_h<1>, cudaFuncAttributeMaxDynamicSharedMemorySize, GEMM_SMEM);
    cudaFuncSetAttribute(attn_kernel, cudaFuncAttributeMaxDynamicSharedMemorySize, ATTN_SMEM);

    __half *xh, *wqh, *wkh, *wvh, *woh;
    cudaGetSymbolAddress((void**)&xh,  g_xh);
    cudaGetSymbolAddress((void**)&wqh, g_wqh);
    cudaGetSymbolAddress((void**)&wkh, g_wkh);
    cudaGetSymbolAddress((void**)&wvh, g_wvh);
    cudaGetSymbolAddress((void**)&woh, g_woh);

    f2h_kernel<<<(M_TOTAL * D_MODEL) / 1024, 256>>>(x,  xh);
    f2h_kernel<<<(D_MODEL * D_MODEL) / 1024, 256>>>(wq, wqh);
    f2h_kernel<<<(D_MODEL * D_MODEL) / 1024, 256>>>(wk, wkh);
    f2h_kernel<<<(D_MODEL * D_MODEL) / 1024, 256>>>(wv, wvh);
    f2h_kernel<<<(D_MODEL * D_MODEL) / 1024, 256>>>(wo, woh);

    dim3 gqkv(D_MODEL / 128, M_TOTAL / 128, 3);
    gemm_h<0><<<gqkv, 256, GEMM_SMEM>>>(nullptr, nullptr);

    dim3 gattn(SEQ / 64, BATCH * NUM_HEADS);
    attn_kernel<<<gattn, 128, ATTN_SMEM>>>();

    dim3 gout(D_MODEL / 128, M_TOTAL / 128, 1);
    gemm_h<1><<<gout, 256, GEMM_SMEM>>>(out, bo);
}

// round 8
// speedup vs baseline: 4.7769x; 1.0226x over previous
#include <cuda_runtime.h>
#include <cuda_fp16.h>
#include <cstdint>
#include <mma.h>
#include <math.h>

using namespace nvcuda;

// Problem constants
#define D_MODEL   1024
#define NUM_HEADS 16
#define HEAD_DIM  64
#define SEQ       2048
#define BATCH     2
#define M_TOTAL   (BATCH * SEQ)   // 4096

// Scratch (no allocation allowed -> __device__ globals)
__device__ __half g_xh[M_TOTAL * D_MODEL];
__device__ __half g_wqh[D_MODEL * D_MODEL];
__device__ __half g_wkh[D_MODEL * D_MODEL];
__device__ __half g_wvh[D_MODEL * D_MODEL];
__device__ __half g_woh[D_MODEL * D_MODEL];
__device__ __half g_q[BATCH * NUM_HEADS * SEQ * HEAD_DIM];   // [B,H,S,Dh]
__device__ __half g_k[BATCH * NUM_HEADS * SEQ * HEAD_DIM];
__device__ __half g_v[BATCH * NUM_HEADS * SEQ * HEAD_DIM];
__device__ __half g_ctx[M_TOTAL * D_MODEL];                  // [B,S,D]

// ---------------------------------------------------------------------------
// helpers
// ---------------------------------------------------------------------------
__device__ __forceinline__ void cp_async16(void* smem_ptr, const void* gmem_ptr) {
    unsigned int s = (unsigned int)__cvta_generic_to_shared(smem_ptr);
    asm volatile("cp.async.cg.shared.global [%0], [%1], 16;\n" :: "r"(s), "l"(gmem_ptr));
}
__device__ __forceinline__ void cp_commit() { asm volatile("cp.async.commit_group;\n"); }
__device__ __forceinline__ void cp_wait0()  { asm volatile("cp.async.wait_group 0;\n"); }
__device__ __forceinline__ void cp_wait1()  { asm volatile("cp.async.wait_group 1;\n"); }

// ---------------------------------------------------------------------------
// float -> half conversions (one-time, DRAM streaming)
// ---------------------------------------------------------------------------
__global__ void __launch_bounds__(256)
f2h_kernel(const float* __restrict__ src, __half* __restrict__ dst)
{
    int i = (blockIdx.x * 256 + threadIdx.x) * 4;
    float4 v = *reinterpret_cast<const float4*>(src + i);
    *reinterpret_cast<__half2*>(dst + i)     = __floats2half2_rn(v.x, v.y);
    *reinterpret_cast<__half2*>(dst + i + 2) = __floats2half2_rn(v.z, v.w);
}

__global__ void __launch_bounds__(256)
w2h_kernel(const float* __restrict__ wq, const float* __restrict__ wk,
           const float* __restrict__ wv, const float* __restrict__ wo)
{
    const float* src;
    __half* dst;
    switch (blockIdx.y) {
        case 0:  src = wq; dst = g_wqh; break;
        case 1:  src = wk; dst = g_wkh; break;
        case 2:  src = wv; dst = g_wvh; break;
        default: src = wo; dst = g_woh; break;
    }
    int i = (blockIdx.x * 256 + threadIdx.x) * 4;
    float4 v = *reinterpret_cast<const float4*>(src + i);
    *reinterpret_cast<__half2*>(dst + i)     = __floats2half2_rn(v.x, v.y);
    *reinterpret_cast<__half2*>(dst + i + 2) = __floats2half2_rn(v.z, v.w);
}

// ---------------------------------------------------------------------------
// fp16 GEMM (unchanged):  Y = X @ W^T
// 128x128x64 tiles, double-buffered cp.async, m16n16k16 wmma, fp32 accum.
// ---------------------------------------------------------------------------
#define BKH 64
#define HS  72   // padded half stride
#define GEMM_SMEM (2 * 2 * 128 * HS * 2)   // 73728 B

template <int MODE>
__global__ void __launch_bounds__(256)
gemm_h(float* __restrict__ Yout, const float* __restrict__ bias)
{
    extern __shared__ __align__(16) char smraw[];
    __half* sm_h = (__half*)smraw;
    float*  sm_f = (float*)smraw;

    const __half* Xp;
    const __half* W;
    __half* Yh = nullptr;
    if (MODE == 0) {
        int which = blockIdx.z;
        W  = (which == 0) ? g_wqh : (which == 1) ? g_wkh : g_wvh;
        Yh = (which == 0) ? g_q   : (which == 1) ? g_k   : g_v;
        Xp = g_xh;
    } else {
        W  = g_woh;
        Xp = g_ctx;
    }

    const int m0 = blockIdx.y * 128;
    const int n0 = blockIdx.x * 128;
    const int tid  = threadIdx.x;
    const int warp = tid >> 5;
    const int wm = warp >> 1;
    const int wn = warp & 1;

    wmma::fragment<wmma::accumulator, 16, 16, 16, float> c[2][4];
#pragma unroll
    for (int i = 0; i < 2; i++)
#pragma unroll
        for (int j = 0; j < 4; j++)
            wmma::fill_fragment(c[i][j], 0.0f);

    const int NIT = D_MODEL / BKH;   // 16

    auto load_stage = [&](int kblk, int s) {
        const int k0 = kblk * BKH;
        __half* Ab = sm_h + s * (2 * 128 * HS);
        __half* Bb = Ab + 128 * HS;
#pragma unroll
        for (int j = 0; j < 4; j++) {
            int idx = tid + j * 256;
            int row = idx >> 3;
            int ch  = idx & 7;
            cp_async16(Ab + row * HS + ch * 8,
                       Xp + (size_t)(m0 + row) * D_MODEL + k0 + ch * 8);
            cp_async16(Bb + row * HS + ch * 8,
                       W  + (size_t)(n0 + row) * D_MODEL + k0 + ch * 8);
        }
        cp_commit();
    };

    load_stage(0, 0);

    for (int it = 0; it < NIT; it++) {
        const int buf = it & 1;
        if (it + 1 < NIT) { load_stage(it + 1, buf ^ 1); cp_wait1(); }
        else              { cp_wait0(); }
        __syncthreads();

        const __half* Ab = sm_h + buf * (2 * 128 * HS);
        const __half* Bb = Ab + 128 * HS;
#pragma unroll
        for (int kk = 0; kk < BKH; kk += 16) {
            wmma::fragment<wmma::matrix_a, 16, 16, 16, __half, wmma::row_major> a[2];
            wmma::fragment<wmma::matrix_b, 16, 16, 16, __half, wmma::col_major> b[4];
#pragma unroll
            for (int i = 0; i < 2; i++)
                wmma::load_matrix_sync(a[i], Ab + (wm * 32 + i * 16) * HS + kk, HS);
#pragma unroll
            for (int j = 0; j < 4; j++)
                wmma::load_matrix_sync(b[j], Bb + (wn * 64 + j * 16) * HS + kk, HS);
#pragma unroll
            for (int i = 0; i < 2; i++)
#pragma unroll
                for (int j = 0; j < 4; j++)
                    wmma::mma_sync(c[i][j], a[i], b[j], c[i][j]);
        }
        __syncthreads();
    }

#pragma unroll
    for (int i = 0; i < 2; i++)
#pragma unroll
        for (int j = 0; j < 4; j++)
            wmma::store_matrix_sync(sm_f + (wm * 32 + i * 16) * 128 + wn * 64 + j * 16,
                                    c[i][j], 128, wmma::mem_row_major);
    __syncthreads();

#pragma unroll
    for (int t = 0; t < 16; t++) {
        int idx = tid + t * 256;
        int row = idx >> 5;
        int c4  = (idx & 31) * 4;
        float4 v = *reinterpret_cast<const float4*>(sm_f + row * 128 + c4);
        const int m = m0 + row;
        const int n = n0 + c4;
        if (MODE == 0) {
            const int b = m >> 11;
            const int s = m & 2047;
            const int h = n >> 6;
            const int d = n & 63;
            __half* dst = Yh + ((size_t)(b * NUM_HEADS + h) * SEQ + s) * HEAD_DIM + d;
            *reinterpret_cast<__half2*>(dst)     = __floats2half2_rn(v.x, v.y);
            *reinterpret_cast<__half2*>(dst + 2) = __floats2half2_rn(v.z, v.w);
        } else {
            float4 bb = *reinterpret_cast<const float4*>(bias + n);
            float4 o = make_float4(v.x + bb.x, v.y + bb.y, v.z + bb.z, v.w + bb.w);
            *reinterpret_cast<float4*>(Yout + (size_t)m * D_MODEL + n) = o;
        }
    }
}

// ---------------------------------------------------------------------------
// Fused causal flash attention v3.
// 256 threads / 8 warps; BQ=128 query rows per CTA (16 rows per warp).
// Warp-private softmax; O accumulator register-resident (32 floats/lane).
// KV double-buffered cp.async. One __syncthreads per 64-key block.
// grid = (S/128, B*H).
// smem layout (bytes):
//   Qs h[128][72]     @ 0       (18432)
//   Ks h[2][64][72]   @ 18432   (18432)
//   Vs h[2][64][72]   @ 36864   (18432)
//   Ss f[8][16][72]   @ 55296   (36864)   per-warp S / PV staging
//   Ps h[8][16][72]   @ 92160   (18432)   per-warp P
#define ATTN_SMEM 110592

__global__ void __launch_bounds__(256, 2)
attn_kernel()
{
    extern __shared__ __align__(16) char smraw[];
    __half* Qs = (__half*)smraw;
    __half* Ks = (__half*)(smraw + 18432);
    __half* Vs = (__half*)(smraw + 36864);
    float*  Ss = (float*)(smraw + 55296);
    __half* Ps = (__half*)(smraw + 92160);

    const int qb = gridDim.x - 1 - blockIdx.x;   // long CTAs first
    const int bh = blockIdx.y;
    const __half* Q = g_q + (size_t)bh * SEQ * HEAD_DIM;
    const __half* K = g_k + (size_t)bh * SEQ * HEAD_DIM;
    const __half* V = g_v + (size_t)bh * SEQ * HEAD_DIM;
    const int q0 = qb * 128;
    const int NKB = 2 * qb + 2;    // 64-key blocks covering keys 0..q0+127

    const int tid  = threadIdx.x;
    const int warp = tid >> 5;
    const int lane = tid & 31;
    const int r    = lane >> 1;    // warp-local row 0..15
    const int hsel = lane & 1;     // 32-col half of the row

    float*  Sw = Ss + warp * 16 * 72;
    __half* Pw = Ps + warp * 16 * 72;

    // loaders (256 threads)
    auto load_q = [&]() {
#pragma unroll
        for (int j = 0; j < 4; j++) {         // 128 rows x 8 chunks = 1024
            int idx = tid + j * 256;
            int row = idx >> 3;
            int ch  = idx & 7;
            cp_async16(Qs + row * HS + ch * 8, Q + (size_t)(q0 + row) * HEAD_DIM + ch * 8);
        }
        cp_commit();
    };
    auto load_kv = [&](int kb, int s) {
        __half* Kb = Ks + s * 64 * HS;
        __half* Vb = Vs + s * 64 * HS;
#pragma unroll
        for (int j = 0; j < 2; j++) {         // 64 rows x 8 chunks = 512 each
            int idx = tid + j * 256;
            int row = idx >> 3;
            int ch  = idx & 7;
            cp_async16(Kb + row * HS + ch * 8, K + (size_t)(kb * 64 + row) * HEAD_DIM + ch * 8);
            cp_async16(Vb + row * HS + ch * 8, V + (size_t)(kb * 64 + row) * HEAD_DIM + ch * 8);
        }
        cp_commit();
    };

    load_q();
    load_kv(0, 0);
    cp_wait0();
    __syncthreads();

    // Q fragments register-resident for the whole kernel (warp rows warp*16..+15)
    wmma::fragment<wmma::matrix_a, 16, 16, 16, __half, wmma::row_major> aq[4];
#pragma unroll
    for (int kk = 0; kk < 4; kk++)
        wmma::load_matrix_sync(aq[kk], Qs + (warp * 16) * HS + kk * 16, HS);

    // per-lane state: row r of this warp, columns hsel*32..+31 of Dh
    float o[32];
#pragma unroll
    for (int t = 0; t < 32; t++) o[t] = 0.0f;
    float m_i = -INFINITY, l_i = 0.0f;
    const int qi = q0 + warp * 16 + r;

    for (int kb = 0; kb < NKB; kb++) {
        const int buf = kb & 1;
        if (kb + 1 < NKB) load_kv(kb + 1, buf ^ 1);

        const __half* Kb = Ks + buf * 64 * HS;
        const __half* Vb = Vs + buf * 64 * HS;

        // ---- S = Q @ K^T (warp-private 16x64) ----
#pragma unroll
        for (int j = 0; j < 4; j++) {
            wmma::fragment<wmma::accumulator, 16, 16, 16, float> cs;
            wmma::fill_fragment(cs, 0.0f);
#pragma unroll
            for (int kk = 0; kk < 4; kk++) {
                wmma::fragment<wmma::matrix_b, 16, 16, 16, __half, wmma::col_major> b;
                wmma::load_matrix_sync(b, Kb + (j * 16) * HS + kk * 16, HS);
                wmma::mma_sync(cs, aq[kk], b, cs);
            }
            wmma::store_matrix_sync(Sw + j * 16, cs, 72, wmma::mem_row_major);
        }
        __syncwarp();

        // ---- online softmax (two-pass; row r, cols hsel*32..+31) ----
        float corr;
        {
            const bool diag = (kb >= 2 * qb);
            const int kbase = kb * 64 + hsel * 32;
            const float* srow = Sw + r * 72 + hsel * 32;
            float mx = -INFINITY;
#pragma unroll
            for (int t = 0; t < 32; t++) {
                float x = srow[t] * 0.125f;   // 1/sqrt(64)
                if (diag && (kbase + t > qi)) x = -INFINITY;
                mx = fmaxf(mx, x);
            }
            mx = fmaxf(mx, __shfl_xor_sync(0xFFFFFFFFu, mx, 1));
            const float mnew = fmaxf(m_i, mx);
            corr = __expf(m_i - mnew);
            float sum = 0.0f;
            __half* prow = Pw + r * 72 + hsel * 32;
#pragma unroll
            for (int t = 0; t < 32; t += 2) {
                bool msk0 = diag && (kbase + t     > qi);
                bool msk1 = diag && (kbase + t + 1 > qi);
                float p0 = msk0 ? 0.0f : __expf(srow[t]     * 0.125f - mnew);
                float p1 = msk1 ? 0.0f : __expf(srow[t + 1] * 0.125f - mnew);
                *reinterpret_cast<__half2*>(prow + t) = __floats2half2_rn(p0, p1);
                sum += p0 + p1;
            }
            sum += __shfl_xor_sync(0xFFFFFFFFu, sum, 1);
            l_i = l_i * corr + sum;
            m_i = mnew;
        }
        __syncwarp();

        // ---- PV: 16x64 tile = P @ V ----
#pragma unroll
        for (int j = 0; j < 4; j++) {
            wmma::fragment<wmma::accumulator, 16, 16, 16, float> co;
            wmma::fill_fragment(co, 0.0f);
#pragma unroll
            for (int kk = 0; kk < 4; kk++) {
                wmma::fragment<wmma::matrix_a, 16, 16, 16, __half, wmma::row_major> a;
                wmma::load_matrix_sync(a, Pw + kk * 16, 72);
                wmma::fragment<wmma::matrix_b, 16, 16, 16, __half, wmma::row_major> b;
                wmma::load_matrix_sync(b, Vb + (kk * 16) * HS + j * 16, HS);
                wmma::mma_sync(co, a, b, co);
            }
            wmma::store_matrix_sync(Sw + j * 16, co, 72, wmma::mem_row_major);
        }
        __syncwarp();

        // ---- O(regs) = O*corr + PV ----
        {
            const float* srow = Sw + r * 72 + hsel * 32;
#pragma unroll
            for (int t = 0; t < 32; t += 4) {
                float4 s = *reinterpret_cast<const float4*>(srow + t);
                o[t]     = o[t]     * corr + s.x;
                o[t + 1] = o[t + 1] * corr + s.y;
                o[t + 2] = o[t + 2] * corr + s.z;
                o[t + 3] = o[t + 3] * corr + s.w;
            }
        }

        if (kb + 1 < NKB) cp_wait0();
        __syncthreads();   // all warps done with buf; prefetch target is free
    }

    // ---- finalize: ctx[b, s, h*64 + d] (half) ----
    {
        const float inv_l = 1.0f / l_i;
        const int b = bh / NUM_HEADS;
        const int h = bh % NUM_HEADS;
        const int s = q0 + warp * 16 + r;
        __half* outp = g_ctx + ((size_t)(b * SEQ + s)) * D_MODEL + h * HEAD_DIM + hsel * 32;
#pragma unroll
        for (int t = 0; t < 32; t += 2)
            *reinterpret_cast<__half2*>(outp + t) =
                __floats2half2_rn(o[t] * inv_l, o[t + 1] * inv_l);
    }
}

// ---------------------------------------------------------------------------
// launch
// ---------------------------------------------------------------------------
extern "C" void kernel_launch(void* const* d_in, const int* in_sizes, int n_in,
                              void* d_out, int out_size)
{
    const float* x  = (const float*)d_in[0];
    const float* wq = (const float*)d_in[1];
    const float* wk = (const float*)d_in[2];
    const float* wv = (const float*)d_in[3];
    const float* wo = (const float*)d_in[4];
    const float* bo = (const float*)d_in[5];
    float* out = (float*)d_out;

    cudaFuncSetAttribute(gemm_h<0>, cudaFuncAttributeMaxDynamicSharedMemorySize, GEMM_SMEM);
    cudaFuncSetAttribute(gemm_h<1>, cudaFuncAttributeMaxDynamicSharedMemorySize, GEMM_SMEM);
    cudaFuncSetAttribute(attn_kernel, cudaFuncAttributeMaxDynamicSharedMemorySize, ATTN_SMEM);

    __half* xh;
    cudaGetSymbolAddress((void**)&xh, g_xh);

    // fp32 -> fp16 converts (x + all 4 weights)
    f2h_kernel<<<(M_TOTAL * D_MODEL) / 1024, 256>>>(x, xh);
    dim3 gw((D_MODEL * D_MODEL) / 1024, 4);
    w2h_kernel<<<gw, 256>>>(wq, wk, wv, wo);

    // QKV projections: grid (N/128, M/128, 3)
    dim3 gqkv(D_MODEL / 128, M_TOTAL / 128, 3);
    gemm_h<0><<<gqkv, 256, GEMM_SMEM>>>(nullptr, nullptr);

    // fused causal attention: BQ=128 per CTA
    dim3 gattn(SEQ / 128, BATCH * NUM_HEADS);
    attn_kernel<<<gattn, 256, ATTN_SMEM>>>();

    // out projection + bias
    dim3 gout(D_MODEL / 128, M_TOTAL / 128, 1);
    gemm_h<1><<<gout, 256, GEMM_SMEM>>>(out, bo);
}

// round 11
// speedup vs baseline: 6.9588x; 1.4568x over previous
#include <cuda_runtime.h>
#include <cuda_fp16.h>
#include <cstdint>
#include <mma.h>
#include <math.h>

using namespace nvcuda;

// Problem constants
#define D_MODEL   1024
#define NUM_HEADS 16
#define HEAD_DIM  64
#define SEQ       2048
#define BATCH     2
#define M_TOTAL   (BATCH * SEQ)   // 4096

// Scratch (no allocation allowed -> __device__ globals)
__device__ __half g_xh[M_TOTAL * D_MODEL];
__device__ __half g_wqh[D_MODEL * D_MODEL];
__device__ __half g_wkh[D_MODEL * D_MODEL];
__device__ __half g_wvh[D_MODEL * D_MODEL];
__device__ __half g_woh[D_MODEL * D_MODEL];
__device__ __half g_q[BATCH * NUM_HEADS * SEQ * HEAD_DIM];   // [B,H,S,Dh]
__device__ __half g_k[BATCH * NUM_HEADS * SEQ * HEAD_DIM];
__device__ __half g_v[BATCH * NUM_HEADS * SEQ * HEAD_DIM];
__device__ __half g_ctx[M_TOTAL * D_MODEL];                  // [B,S,D]

// ---------------------------------------------------------------------------
// helpers
// ---------------------------------------------------------------------------
__device__ __forceinline__ void cp_async16(void* smem_ptr, const void* gmem_ptr) {
    unsigned int s = (unsigned int)__cvta_generic_to_shared(smem_ptr);
    asm volatile("cp.async.cg.shared.global [%0], [%1], 16;\n" :: "r"(s), "l"(gmem_ptr));
}
__device__ __forceinline__ void cp_commit() { asm volatile("cp.async.commit_group;\n"); }
__device__ __forceinline__ void cp_wait0()  { asm volatile("cp.async.wait_group 0;\n"); }
__device__ __forceinline__ void cp_wait1()  { asm volatile("cp.async.wait_group 1;\n"); }

__device__ __forceinline__ unsigned smem_u32(const void* p) {
    return (unsigned)__cvta_generic_to_shared(p);
}

__device__ __forceinline__ void ldsm4(uint32_t& r0, uint32_t& r1, uint32_t& r2, uint32_t& r3,
                                      unsigned a) {
    asm volatile("ldmatrix.sync.aligned.m8n8.x4.shared.b16 {%0,%1,%2,%3}, [%4];"
                 : "=r"(r0), "=r"(r1), "=r"(r2), "=r"(r3) : "r"(a));
}
__device__ __forceinline__ void ldsm4t(uint32_t& r0, uint32_t& r1, uint32_t& r2, uint32_t& r3,
                                       unsigned a) {
    asm volatile("ldmatrix.sync.aligned.m8n8.x4.trans.shared.b16 {%0,%1,%2,%3}, [%4];"
                 : "=r"(r0), "=r"(r1), "=r"(r2), "=r"(r3) : "r"(a));
}
__device__ __forceinline__ void mma_16816(float c[4], const uint32_t a[4], const uint32_t b[2]) {
    asm volatile(
        "mma.sync.aligned.m16n8k16.row.col.f32.f16.f16.f32 "
        "{%0,%1,%2,%3}, {%4,%5,%6,%7}, {%8,%9}, {%0,%1,%2,%3};"
        : "+f"(c[0]), "+f"(c[1]), "+f"(c[2]), "+f"(c[3])
        : "r"(a[0]), "r"(a[1]), "r"(a[2]), "r"(a[3]), "r"(b[0]), "r"(b[1]));
}
__device__ __forceinline__ uint32_t h2pack(float x, float y) {
    __half2 h = __floats2half2_rn(x, y);
    return *reinterpret_cast<uint32_t*>(&h);
}

// ---------------------------------------------------------------------------
// float -> half conversions (one-time, DRAM streaming)
// ---------------------------------------------------------------------------
__global__ void __launch_bounds__(256)
f2h_kernel(const float* __restrict__ src, __half* __restrict__ dst)
{
    int i = (blockIdx.x * 256 + threadIdx.x) * 4;
    float4 v = *reinterpret_cast<const float4*>(src + i);
    *reinterpret_cast<__half2*>(dst + i)     = __floats2half2_rn(v.x, v.y);
    *reinterpret_cast<__half2*>(dst + i + 2) = __floats2half2_rn(v.z, v.w);
}

__global__ void __launch_bounds__(256)
w2h_kernel(const float* __restrict__ wq, const float* __restrict__ wk,
           const float* __restrict__ wv, const float* __restrict__ wo)
{
    const float* src;
    __half* dst;
    switch (blockIdx.y) {
        case 0:  src = wq; dst = g_wqh; break;
        case 1:  src = wk; dst = g_wkh; break;
        case 2:  src = wv; dst = g_wvh; break;
        default: src = wo; dst = g_woh; break;
    }
    int i = (blockIdx.x * 256 + threadIdx.x) * 4;
    float4 v = *reinterpret_cast<const float4*>(src + i);
    *reinterpret_cast<__half2*>(dst + i)     = __floats2half2_rn(v.x, v.y);
    *reinterpret_cast<__half2*>(dst + i + 2) = __floats2half2_rn(v.z, v.w);
}

// ---------------------------------------------------------------------------
// fp16 GEMM (unchanged):  Y = X @ W^T
// ---------------------------------------------------------------------------
#define BKH 64
#define HS  72   // padded half stride
#define GEMM_SMEM (2 * 2 * 128 * HS * 2)   // 73728 B

template <int MODE>
__global__ void __launch_bounds__(256)
gemm_h(float* __restrict__ Yout, const float* __restrict__ bias)
{
    extern __shared__ __align__(16) char smraw[];
    __half* sm_h = (__half*)smraw;
    float*  sm_f = (float*)smraw;

    const __half* Xp;
    const __half* W;
    __half* Yh = nullptr;
    if (MODE == 0) {
        int which = blockIdx.z;
        W  = (which == 0) ? g_wqh : (which == 1) ? g_wkh : g_wvh;
        Yh = (which == 0) ? g_q   : (which == 1) ? g_k   : g_v;
        Xp = g_xh;
    } else {
        W  = g_woh;
        Xp = g_ctx;
    }

    const int m0 = blockIdx.y * 128;
    const int n0 = blockIdx.x * 128;
    const int tid  = threadIdx.x;
    const int warp = tid >> 5;
    const int wm = warp >> 1;
    const int wn = warp & 1;

    wmma::fragment<wmma::accumulator, 16, 16, 16, float> c[2][4];
#pragma unroll
    for (int i = 0; i < 2; i++)
#pragma unroll
        for (int j = 0; j < 4; j++)
            wmma::fill_fragment(c[i][j], 0.0f);

    const int NIT = D_MODEL / BKH;   // 16

    auto load_stage = [&](int kblk, int s) {
        const int k0 = kblk * BKH;
        __half* Ab = sm_h + s * (2 * 128 * HS);
        __half* Bb = Ab + 128 * HS;
#pragma unroll
        for (int j = 0; j < 4; j++) {
            int idx = tid + j * 256;
            int row = idx >> 3;
            int ch  = idx & 7;
            cp_async16(Ab + row * HS + ch * 8,
                       Xp + (size_t)(m0 + row) * D_MODEL + k0 + ch * 8);
            cp_async16(Bb + row * HS + ch * 8,
                       W  + (size_t)(n0 + row) * D_MODEL + k0 + ch * 8);
        }
        cp_commit();
    };

    load_stage(0, 0);

    for (int it = 0; it < NIT; it++) {
        const int buf = it & 1;
        if (it + 1 < NIT) { load_stage(it + 1, buf ^ 1); cp_wait1(); }
        else              { cp_wait0(); }
        __syncthreads();

        const __half* Ab = sm_h + buf * (2 * 128 * HS);
        const __half* Bb = Ab + 128 * HS;
#pragma unroll
        for (int kk = 0; kk < BKH; kk += 16) {
            wmma::fragment<wmma::matrix_a, 16, 16, 16, __half, wmma::row_major> a[2];
            wmma::fragment<wmma::matrix_b, 16, 16, 16, __half, wmma::col_major> b[4];
#pragma unroll
            for (int i = 0; i < 2; i++)
                wmma::load_matrix_sync(a[i], Ab + (wm * 32 + i * 16) * HS + kk, HS);
#pragma unroll
            for (int j = 0; j < 4; j++)
                wmma::load_matrix_sync(b[j], Bb + (wn * 64 + j * 16) * HS + kk, HS);
#pragma unroll
            for (int i = 0; i < 2; i++)
#pragma unroll
                for (int j = 0; j < 4; j++)
                    wmma::mma_sync(c[i][j], a[i], b[j], c[i][j]);
        }
        __syncthreads();
    }

#pragma unroll
    for (int i = 0; i < 2; i++)
#pragma unroll
        for (int j = 0; j < 4; j++)
            wmma::store_matrix_sync(sm_f + (wm * 32 + i * 16) * 128 + wn * 64 + j * 16,
                                    c[i][j], 128, wmma::mem_row_major);
    __syncthreads();

#pragma unroll
    for (int t = 0; t < 16; t++) {
        int idx = tid + t * 256;
        int row = idx >> 5;
        int c4  = (idx & 31) * 4;
        float4 v = *reinterpret_cast<const float4*>(sm_f + row * 128 + c4);
        const int m = m0 + row;
        const int n = n0 + c4;
        if (MODE == 0) {
            const int b = m >> 11;
            const int s = m & 2047;
            const int h = n >> 6;
            const int d = n & 63;
            __half* dst = Yh + ((size_t)(b * NUM_HEADS + h) * SEQ + s) * HEAD_DIM + d;
            *reinterpret_cast<__half2*>(dst)     = __floats2half2_rn(v.x, v.y);
            *reinterpret_cast<__half2*>(dst + 2) = __floats2half2_rn(v.z, v.w);
        } else {
            float4 bb = *reinterpret_cast<const float4*>(bias + n);
            float4 o = make_float4(v.x + bb.x, v.y + bb.y, v.z + bb.z, v.w + bb.w);
            *reinterpret_cast<float4*>(Yout + (size_t)m * D_MODEL + n) = o;
        }
    }
}

// ---------------------------------------------------------------------------
// Fused causal flash attention v4 — FA2-style register pipeline, raw mma.sync.
// 256 threads / 8 warps; BQ=128 (16 rows/warp). S, P, O register-resident.
// K via ldmatrix (plain), V via ldmatrix.trans. KV double-buffered cp.async.
// grid = (S/128, B*H).
// smem: Qs h[128][72] @0 (18432) | Ks h[2][64][72] @18432 | Vs h[2][64][72] @36864
#define ATTN_SMEM 55296

__global__ void __launch_bounds__(256, 2)
attn_kernel()
{
    extern __shared__ __align__(16) char smraw[];
    __half* Qs = (__half*)smraw;
    __half* Ks = (__half*)(smraw + 18432);
    __half* Vs = (__half*)(smraw + 36864);

    const int qb = gridDim.x - 1 - blockIdx.x;   // long CTAs first
    const int bh = blockIdx.y;
    const __half* Q = g_q + (size_t)bh * SEQ * HEAD_DIM;
    const __half* K = g_k + (size_t)bh * SEQ * HEAD_DIM;
    const __half* V = g_v + (size_t)bh * SEQ * HEAD_DIM;
    const int q0 = qb * 128;
    const int NKB = 2 * qb + 2;    // 64-key blocks covering keys 0..q0+127

    const int tid  = threadIdx.x;
    const int warp = tid >> 5;
    const int lane = tid & 31;
    const int lr   = lane >> 2;        // tile row 0..7
    const int lc   = (lane & 3) * 2;   // tile col pair base

    // loaders (256 threads)
    auto load_q = [&]() {
#pragma unroll
        for (int j = 0; j < 4; j++) {
            int idx = tid + j * 256;
            int row = idx >> 3;
            int ch  = idx & 7;
            cp_async16(Qs + row * HS + ch * 8, Q + (size_t)(q0 + row) * HEAD_DIM + ch * 8);
        }
        cp_commit();
    };
    auto load_kv = [&](int kb, int s) {
        __half* Kb = Ks + s * 64 * HS;
        __half* Vb = Vs + s * 64 * HS;
#pragma unroll
        for (int j = 0; j < 2; j++) {
            int idx = tid + j * 256;
            int row = idx >> 3;
            int ch  = idx & 7;
            cp_async16(Kb + row * HS + ch * 8, K + (size_t)(kb * 64 + row) * HEAD_DIM + ch * 8);
            cp_async16(Vb + row * HS + ch * 8, V + (size_t)(kb * 64 + row) * HEAD_DIM + ch * 8);
        }
        cp_commit();
    };

    load_q();
    load_kv(0, 0);
    cp_wait0();
    __syncthreads();

    // Q A-fragments (m16n8k16), register-resident for whole kernel.
    uint32_t Qa[4][4];
    {
        const unsigned qbase = smem_u32(Qs);
        const int row = warp * 16 + (lane & 7) + ((lane >> 3) & 1) * 8;
        const int csel = (lane >> 4) * 8;
#pragma unroll
        for (int kt = 0; kt < 4; kt++)
            ldsm4(Qa[kt][0], Qa[kt][1], Qa[kt][2], Qa[kt][3],
                  qbase + (unsigned)(row * HS + kt * 16 + csel) * 2);
    }

    float O[8][4];
#pragma unroll
    for (int nt = 0; nt < 8; nt++)
#pragma unroll
        for (int i = 0; i < 4; i++) O[nt][i] = 0.0f;
    float m0 = -INFINITY, m1 = -INFINITY, l0 = 0.0f, l1 = 0.0f;
    const int qi0 = q0 + warp * 16 + lr;
    const int qi1 = qi0 + 8;
    const int qmin = q0 + warp * 16;
    const int qmax = qmin + 15;

    for (int kb = 0; kb < NKB; kb++) {
        const int buf = kb & 1;
        if (kb + 1 < NKB) load_kv(kb + 1, buf ^ 1);

        const __half* Kb = Ks + buf * 64 * HS;
        const __half* Vb = Vs + buf * 64 * HS;
        const int kbase = kb * 64;

        if (kbase <= qmax) {   // block not fully masked for this warp
            // ---- S = Q @ K^T : 8 n-tiles of m16n8, K as B-frags (plain ldmatrix) ----
            float S[8][4];
#pragma unroll
            for (int nt = 0; nt < 8; nt++)
#pragma unroll
                for (int i = 0; i < 4; i++) S[nt][i] = 0.0f;
            {
                const unsigned kb_s = smem_u32(Kb);
                const int krow = (lane & 7) + (lane >> 4) * 8;
                const int kcol = ((lane >> 3) & 1) * 8;
#pragma unroll
                for (int kt = 0; kt < 4; kt++) {
                    uint32_t KB[16];
#pragma unroll
                    for (int g = 0; g < 4; g++)
                        ldsm4(KB[g * 4], KB[g * 4 + 1], KB[g * 4 + 2], KB[g * 4 + 3],
                              kb_s + (unsigned)((g * 16 + krow) * HS + kt * 16 + kcol) * 2);
#pragma unroll
                    for (int nt = 0; nt < 8; nt++)
                        mma_16816(S[nt], Qa[kt], &KB[nt * 2]);
                }
            }

            // ---- online softmax on registers ----
            const float scale = 0.125f;   // 1/sqrt(64)
            float mx0 = -INFINITY, mx1 = -INFINITY;
            if (kbase + 63 > qmin) {      // diagonal block: elementwise mask
#pragma unroll
                for (int nt = 0; nt < 8; nt++) {
                    const int c0 = kbase + nt * 8 + lc;
                    float x0 = (c0     <= qi0) ? S[nt][0] * scale : -INFINITY;
                    float x1 = (c0 + 1 <= qi0) ? S[nt][1] * scale : -INFINITY;
                    float x2 = (c0     <= qi1) ? S[nt][2] * scale : -INFINITY;
                    float x3 = (c0 + 1 <= qi1) ? S[nt][3] * scale : -INFINITY;
                    S[nt][0] = x0; S[nt][1] = x1; S[nt][2] = x2; S[nt][3] = x3;
                    mx0 = fmaxf(mx0, fmaxf(x0, x1));
                    mx1 = fmaxf(mx1, fmaxf(x2, x3));
                }
            } else {
#pragma unroll
                for (int nt = 0; nt < 8; nt++) {
                    S[nt][0] *= scale; S[nt][1] *= scale;
                    S[nt][2] *= scale; S[nt][3] *= scale;
                    mx0 = fmaxf(mx0, fmaxf(S[nt][0], S[nt][1]));
                    mx1 = fmaxf(mx1, fmaxf(S[nt][2], S[nt][3]));
                }
            }
            mx0 = fmaxf(mx0, __shfl_xor_sync(0xFFFFFFFFu, mx0, 1));
            mx0 = fmaxf(mx0, __shfl_xor_sync(0xFFFFFFFFu, mx0, 2));
            mx1 = fmaxf(mx1, __shfl_xor_sync(0xFFFFFFFFu, mx1, 1));
            mx1 = fmaxf(mx1, __shfl_xor_sync(0xFFFFFFFFu, mx1, 2));
            const float mn0 = fmaxf(m0, mx0);
            const float mn1 = fmaxf(m1, mx1);
            const float corr0 = __expf(m0 - mn0);
            const float corr1 = __expf(m1 - mn1);

            // P (half) packed directly as A-fragments for PV
            uint32_t Pa[4][4];
            float s0 = 0.0f, s1 = 0.0f;
#pragma unroll
            for (int kt = 0; kt < 4; kt++) {
                float p00 = __expf(S[2 * kt][0] - mn0);
                float p01 = __expf(S[2 * kt][1] - mn0);
                float p02 = __expf(S[2 * kt][2] - mn1);
                float p03 = __expf(S[2 * kt][3] - mn1);
                float p10 = __expf(S[2 * kt + 1][0] - mn0);
                float p11 = __expf(S[2 * kt + 1][1] - mn0);
                float p12 = __expf(S[2 * kt + 1][2] - mn1);
                float p13 = __expf(S[2 * kt + 1][3] - mn1);
                Pa[kt][0] = h2pack(p00, p01);
                Pa[kt][1] = h2pack(p02, p03);
                Pa[kt][2] = h2pack(p10, p11);
                Pa[kt][3] = h2pack(p12, p13);
                s0 += p00 + p01 + p10 + p11;
                s1 += p02 + p03 + p12 + p13;
            }
            s0 += __shfl_xor_sync(0xFFFFFFFFu, s0, 1);
            s0 += __shfl_xor_sync(0xFFFFFFFFu, s0, 2);
            s1 += __shfl_xor_sync(0xFFFFFFFFu, s1, 1);
            s1 += __shfl_xor_sync(0xFFFFFFFFu, s1, 2);
            l0 = l0 * corr0 + s0;
            l1 = l1 * corr1 + s1;
            m0 = mn0; m1 = mn1;

            // ---- O rescale + PV (V as B-frags via ldmatrix.trans) ----
#pragma unroll
            for (int nt = 0; nt < 8; nt++) {
                O[nt][0] *= corr0; O[nt][1] *= corr0;
                O[nt][2] *= corr1; O[nt][3] *= corr1;
            }
            {
                const unsigned vb_s = smem_u32(Vb);
                const int vrow = (lane & 7) + ((lane >> 3) & 1) * 8;
                const int vcol = (lane >> 4) * 8;
#pragma unroll
                for (int kt = 0; kt < 4; kt++) {
                    uint32_t VB[16];
#pragma unroll
                    for (int g = 0; g < 4; g++)
                        ldsm4t(VB[g * 4], VB[g * 4 + 1], VB[g * 4 + 2], VB[g * 4 + 3],
                               vb_s + (unsigned)((kt * 16 + vrow) * HS + g * 16 + vcol) * 2);
#pragma unroll
                    for (int nt = 0; nt < 8; nt++)
                        mma_16816(O[nt], Pa[kt], &VB[nt * 2]);
                }
            }
        }

        if (kb + 1 < NKB) cp_wait0();
        __syncthreads();   // all warps done with buf; prefetch target free
    }

    // ---- finalize: ctx[b, s, h*64 + d] (half) ----
    {
        const float inv0 = 1.0f / l0;
        const float inv1 = 1.0f / l1;
        const int b = bh / NUM_HEADS;
        const int h = bh % NUM_HEADS;
        __half* o0 = g_ctx + (size_t)(b * SEQ + qi0) * D_MODEL + h * HEAD_DIM + lc;
        __half* o1 = g_ctx + (size_t)(b * SEQ + qi1) * D_MODEL + h * HEAD_DIM + lc;
#pragma unroll
        for (int nt = 0; nt < 8; nt++) {
            *reinterpret_cast<__half2*>(o0 + nt * 8) =
                __floats2half2_rn(O[nt][0] * inv0, O[nt][1] * inv0);
            *reinterpret_cast<__half2*>(o1 + nt * 8) =
                __floats2half2_rn(O[nt][2] * inv1, O[nt][3] * inv1);
        }
    }
}

// ---------------------------------------------------------------------------
// launch
// ---------------------------------------------------------------------------
extern "C" void kernel_launch(void* const* d_in, const int* in_sizes, int n_in,
                              void* d_out, int out_size)
{
    const float* x  = (const float*)d_in[0];
    const float* wq = (const float*)d_in[1];
    const float* wk = (const float*)d_in[2];
    const float* wv = (const float*)d_in[3];
    const float* wo = (const float*)d_in[4];
    const float* bo = (const float*)d_in[5];
    float* out = (float*)d_out;

    cudaFuncSetAttribute(gemm_h<0>, cudaFuncAttributeMaxDynamicSharedMemorySize, GEMM_SMEM);
    cudaFuncSetAttribute(gemm_h<1>, cudaFuncAttributeMaxDynamicSharedMemorySize, GEMM_SMEM);
    cudaFuncSetAttribute(attn_kernel, cudaFuncAttributeMaxDynamicSharedMemorySize, ATTN_SMEM);

    __half* xh;
    cudaGetSymbolAddress((void**)&xh, g_xh);

    f2h_kernel<<<(M_TOTAL * D_MODEL) / 1024, 256>>>(x, xh);
    dim3 gw((D_MODEL * D_MODEL) / 1024, 4);
    w2h_kernel<<<gw, 256>>>(wq, wk, wv, wo);

    dim3 gqkv(D_MODEL / 128, M_TOTAL / 128, 3);
    gemm_h<0><<<gqkv, 256, GEMM_SMEM>>>(nullptr, nullptr);

    dim3 gattn(SEQ / 128, BATCH * NUM_HEADS);
    attn_kernel<<<gattn, 256, ATTN_SMEM>>>();

    dim3 gout(D_MODEL / 128, M_TOTAL / 128, 1);
    gemm_h<1><<<gout, 256, GEMM_SMEM>>>(out, bo);
}